// round 11
// baseline (speedup 1.0000x reference)
#include <cuda_runtime.h>
#include <cuda_fp16.h>
#include <cstdint>

#define Bn 4
#define Cn 256
#define Hn 128
#define Wn 256
#define HWn 32768
#define PS 72    // smem stride (halves), 64-wide tiles
#define PSV 264  // smem stride (halves), 256-wide rows

// q,k pre-split hi/lo fp16 [b][p][64]; v plain fp16 [b][o][p]
__device__ __half g_qh[(size_t)Bn * HWn * 64];
__device__ __half g_ql[(size_t)Bn * HWn * 64];
__device__ __half g_kh[(size_t)Bn * HWn * 64];
__device__ __half g_kl[(size_t)Bn * HWn * 64];
__device__ __half g_v [(size_t)Bn * 256 * HWn];
// pre-converted weights
__device__ __half g_wqh[64 * 256], g_wql[64 * 256];
__device__ __half g_wkh[64 * 256], g_wkl[64 * 256];
__device__ __half g_wv16[256 * 256];

// ---------------- helpers ----------------
static __device__ __forceinline__ void split2(float x, __half& h, __half& l) {
    h = __float2half_rn(x);
    l = __float2half_rn(x - __half2float(h));
}
static __device__ __forceinline__ uint32_t pack2(__half a, __half b) {
    __half2 t = __halves2half2(a, b);
    return *(uint32_t*)&t;
}
static __device__ __forceinline__ uint32_t sptr(const void* p) {
    return (uint32_t)__cvta_generic_to_shared(p);
}
static __device__ __forceinline__ void mma16816(float* d, const uint32_t* a, const uint32_t* b) {
    asm volatile("mma.sync.aligned.m16n8k16.row.col.f32.f16.f16.f32 "
        "{%0,%1,%2,%3}, {%4,%5,%6,%7}, {%8,%9}, {%0,%1,%2,%3};"
        : "+f"(d[0]), "+f"(d[1]), "+f"(d[2]), "+f"(d[3])
        : "r"(a[0]), "r"(a[1]), "r"(a[2]), "r"(a[3]), "r"(b[0]), "r"(b[1]));
}
static __device__ __forceinline__ void ldmA(uint32_t* a, const __half* t, int m0, int k0,
                                            int lane, int stride) {
    const __half* p = t + (m0 + (lane & 15)) * stride + k0 + ((lane >> 4) << 3);
    asm volatile("ldmatrix.sync.aligned.m8n8.x4.shared.b16 {%0,%1,%2,%3}, [%4];"
        : "=r"(a[0]), "=r"(a[1]), "=r"(a[2]), "=r"(a[3]) : "r"(sptr(p)));
}
static __device__ __forceinline__ void ldmB2(uint32_t* b, const __half* t, int n0, int k0,
                                             int lane, int stride) {
    int grp = lane >> 3;
    const __half* p = t + (n0 + ((grp & 2) << 2) + (lane & 7)) * stride + k0 + ((grp & 1) << 3);
    asm volatile("ldmatrix.sync.aligned.m8n8.x4.shared.b16 {%0,%1,%2,%3}, [%4];"
        : "=r"(b[0]), "=r"(b[1]), "=r"(b[2]), "=r"(b[3]) : "r"(sptr(p)));
}
#define CP16(d, s)  asm volatile("cp.async.cg.shared.global [%0], [%1], 16;" :: "r"(d), "l"(s))
#define CPCOMMIT()  asm volatile("cp.async.commit_group;")
#define CPWAIT(n)   asm volatile("cp.async.wait_group %0;" :: "n"(n) : "memory")

// ---------------------------------------------------------------------------
// prep: Wq/Wk -> hi/lo fp16, Wv -> fp16
// ---------------------------------------------------------------------------
__global__ void prep(const float* __restrict__ Wq, const float* __restrict__ Wk,
                     const float* __restrict__ Wv)
{
    int i = (blockIdx.x * 256 + threadIdx.x) * 2;
    __half h0, l0, h1, l1;
    if (i < 16384) {
        split2(Wq[i], h0, l0); split2(Wq[i + 1], h1, l1);
        *(uint32_t*)&g_wqh[i] = pack2(h0, h1);
        *(uint32_t*)&g_wql[i] = pack2(l0, l1);
    } else if (i < 32768) {
        int j = i - 16384;
        split2(Wk[j], h0, l0); split2(Wk[j + 1], h1, l1);
        *(uint32_t*)&g_wkh[j] = pack2(h0, h1);
        *(uint32_t*)&g_wkl[j] = pack2(l0, l1);
    } else {
        int j = i - 32768;
        *(uint32_t*)&g_wv16[j] = pack2(__float2half_rn(Wv[j]), __float2half_rn(Wv[j + 1]));
    }
}

// ---------------------------------------------------------------------------
// q projection (3-term split): D[128 p, 64 d] = de_out^T * Wq^T + bq
// grid (HWn/128, 1, B), 256 threads. (R10 qk_proj, q-only)
// ---------------------------------------------------------------------------
#define Q_SMEM 73728
__global__ __launch_bounds__(256) void q_proj(
    const float* __restrict__ de_out, const float* __restrict__ bq)
{
    extern __shared__ __half smh[];
    __half* xh = smh;
    __half* xl = smh + 9216;

    const int tid = threadIdx.x, w = tid >> 5, lane = tid & 31;
    const int c = lane & 3, g = lane >> 2;
    const int wm = w & 3, wn = w >> 2;
    const int p0 = blockIdx.x * 128, b = blockIdx.z;
    const float* Xb = de_out + (size_t)b * Cn * HWn;

    float acc[2][4][4] = {};

    {
        __half* wb = smh + 18432;
        for (int i = tid; i < 512; i += 256) {
            int d = i >> 3, s = (i & 7) * 8;
            CP16(sptr(wb + d * PS + s), g_wqh + d * 256 + s);
            CP16(sptr(wb + 4608 + d * PS + s), g_wql + d * 256 + s);
        }
        CPCOMMIT();
    }

    for (int kc = 0; kc < 4; kc++) {
        if (kc < 3) {
            __half* wb = smh + 18432 + ((kc + 1) & 1) * 9216;
            for (int i = tid; i < 512; i += 256) {
                int d = i >> 3, s = (i & 7) * 8;
                CP16(sptr(wb + d * PS + s), g_wqh + d * 256 + (kc + 1) * 64 + s);
                CP16(sptr(wb + 4608 + d * PS + s), g_wql + d * 256 + (kc + 1) * 64 + s);
            }
            CPCOMMIT();
        }
        for (int i = tid; i < 2048; i += 256) {
            int p = i & 127, cg = i >> 7;
            const float* src = &Xb[(size_t)(kc * 64 + cg * 4) * HWn + p0 + p];
            __half h0, l0, h1, l1;
            uint2 hv, lv;
            split2(src[0], h0, l0);
            split2(src[(size_t)HWn], h1, l1);
            hv.x = pack2(h0, h1); lv.x = pack2(l0, l1);
            split2(src[2 * (size_t)HWn], h0, l0);
            split2(src[3 * (size_t)HWn], h1, l1);
            hv.y = pack2(h0, h1); lv.y = pack2(l0, l1);
            *(uint2*)&xh[p * PS + cg * 4] = hv;
            *(uint2*)&xl[p * PS + cg * 4] = lv;
        }
        if (kc < 3) CPWAIT(1); else CPWAIT(0);
        __syncthreads();

        const __half* wh = smh + 18432 + (kc & 1) * 9216;
        const __half* wl = wh + 4608;
#pragma unroll
        for (int kt = 0; kt < 4; kt++) {
            uint32_t ah0[4], al0[4], ah1[4], al1[4];
            ldmA(ah0, xh, wm * 32, kt * 16, lane, PS);
            ldmA(al0, xl, wm * 32, kt * 16, lane, PS);
            ldmA(ah1, xh, wm * 32 + 16, kt * 16, lane, PS);
            ldmA(al1, xl, wm * 32 + 16, kt * 16, lane, PS);
#pragma unroll
            for (int nt = 0; nt < 4; nt += 2) {
                uint32_t bh[4], bl[4];
                ldmB2(bh, wh, wn * 32 + nt * 8, kt * 16, lane, PS);
                ldmB2(bl, wl, wn * 32 + nt * 8, kt * 16, lane, PS);
                mma16816(acc[0][nt], ah0, bh);
                mma16816(acc[0][nt], ah0, bl);
                mma16816(acc[0][nt], al0, bh);
                mma16816(acc[1][nt], ah1, bh);
                mma16816(acc[1][nt], ah1, bl);
                mma16816(acc[1][nt], al1, bh);
                mma16816(acc[0][nt + 1], ah0, bh + 2);
                mma16816(acc[0][nt + 1], ah0, bl + 2);
                mma16816(acc[0][nt + 1], al0, bh + 2);
                mma16816(acc[1][nt + 1], ah1, bh + 2);
                mma16816(acc[1][nt + 1], ah1, bl + 2);
                mma16816(acc[1][nt + 1], al1, bh + 2);
            }
        }
        __syncthreads();
    }
#pragma unroll
    for (int mt = 0; mt < 2; mt++) {
#pragma unroll
        for (int nt = 0; nt < 4; nt++) {
            int dcol = wn * 32 + nt * 8 + 2 * c;
            float b0 = bq[dcol], b1 = bq[dcol + 1];
            size_t r0 = ((size_t)b * HWn + p0 + wm * 32 + mt * 16 + g) * 64 + dcol;
            size_t r1 = r0 + (size_t)8 * 64;
            __half h0, l0, h1, l1;
            split2(acc[mt][nt][0] + b0, h0, l0);
            split2(acc[mt][nt][1] + b1, h1, l1);
            *(uint32_t*)&g_qh[r0] = pack2(h0, h1);
            *(uint32_t*)&g_ql[r0] = pack2(l0, l1);
            split2(acc[mt][nt][2] + b0, h0, l0);
            split2(acc[mt][nt][3] + b1, h1, l1);
            *(uint32_t*)&g_qh[r1] = pack2(h0, h1);
            *(uint32_t*)&g_ql[r1] = pack2(l0, l1);
        }
    }
}

// ---------------------------------------------------------------------------
// FUSED k+v projection from flow. grid (HWn/128, 1, B), 512 threads.
// X staged ONCE as hi/lo slab [128p][256c] (2x67584 B). Phase A: k (3-term,
// full Wk hi/lo resident). Phase B: v (1-term from hi slab, Wv tiles
// double-buffered). smem total 202752 B.
// ---------------------------------------------------------------------------
#define KV_SMEM (67584 * 3)
static __device__ __forceinline__ void issue_wv_tile(__half* smh, int tid, int t) {
    __half* wb = smh + 67584 + (t & 1) * 9216;
    int oh = t >> 2, kc = t & 3;
    for (int i = tid; i < 1024; i += 512) {
        int o = i >> 3, s = (i & 7) * 8;
        CP16(sptr(wb + o * PS + s), g_wv16 + (size_t)(oh * 128 + o) * 256 + kc * 64 + s);
    }
    CPCOMMIT();
}
__global__ __launch_bounds__(512) void kv_proj(
    const float* __restrict__ flow, const float* __restrict__ bk,
    const float* __restrict__ bv)
{
    extern __shared__ __half smh[];
    __half* xh = smh;                    // [128][264]
    __half* xl = smh + 33792;            // [128][264]
    __half* wkh = smh + 67584;           // phase A: [64][264]
    __half* wkl = smh + 67584 + 16896;

    const int tid = threadIdx.x, w = tid >> 5, lane = tid & 31;
    const int c = lane & 3, g = lane >> 2;
    const int wm = w & 3, wn = w >> 2;   // 4m x 4n
    const int p0 = blockIdx.x * 128, b = blockIdx.z;
    const float* Xb = flow + (size_t)b * Cn * HWn;

    // issue full Wk hi/lo
    for (int i = tid; i < 2048; i += 512) {
        int d = i >> 5, s = (i & 31) * 8;
        CP16(sptr(wkh + d * PSV + s), g_wkh + d * 256 + s);
        CP16(sptr(wkl + d * PSV + s), g_wkl + d * 256 + s);
    }
    CPCOMMIT();

    // stage X slab hi/lo [128p][256c] (overlaps Wk DMA)
    for (int i = tid; i < 8192; i += 512) {
        int p = i & 127, cg = i >> 7;
        const float* src = &Xb[(size_t)(cg * 4) * HWn + p0 + p];
        __half h0, l0, h1, l1;
        uint2 hv, lv;
        split2(src[0], h0, l0);
        split2(src[(size_t)HWn], h1, l1);
        hv.x = pack2(h0, h1); lv.x = pack2(l0, l1);
        split2(src[2 * (size_t)HWn], h0, l0);
        split2(src[3 * (size_t)HWn], h1, l1);
        hv.y = pack2(h0, h1); lv.y = pack2(l0, l1);
        *(uint2*)&xh[p * PSV + cg * 4] = hv;
        *(uint2*)&xl[p * PSV + cg * 4] = lv;
    }
    CPWAIT(0);
    __syncthreads();

    // ---- Phase A: k = X * Wk^T (3-term), pure MMA burst ----
    {
        float acc[2][2][4] = {};
#pragma unroll
        for (int kc = 0; kc < 4; kc++) {
#pragma unroll
            for (int kt = 0; kt < 4; kt++) {
                int k0 = kc * 64 + kt * 16;
                uint32_t ah0[4], al0[4], ah1[4], al1[4], bh[4], bl[4];
                ldmA(ah0, xh, wm * 32, k0, lane, PSV);
                ldmA(al0, xl, wm * 32, k0, lane, PSV);
                ldmA(ah1, xh, wm * 32 + 16, k0, lane, PSV);
                ldmA(al1, xl, wm * 32 + 16, k0, lane, PSV);
                ldmB2(bh, wkh, wn * 16, k0, lane, PSV);
                ldmB2(bl, wkl, wn * 16, k0, lane, PSV);
                mma16816(acc[0][0], ah0, bh);
                mma16816(acc[0][0], ah0, bl);
                mma16816(acc[0][0], al0, bh);
                mma16816(acc[1][0], ah1, bh);
                mma16816(acc[1][0], ah1, bl);
                mma16816(acc[1][0], al1, bh);
                mma16816(acc[0][1], ah0, bh + 2);
                mma16816(acc[0][1], ah0, bl + 2);
                mma16816(acc[0][1], al0, bh + 2);
                mma16816(acc[1][1], ah1, bh + 2);
                mma16816(acc[1][1], ah1, bl + 2);
                mma16816(acc[1][1], al1, bh + 2);
            }
        }
        __syncthreads();              // all warps done reading Wk
        issue_wv_tile(smh, tid, 0);   // start v W DMA under epilogue
        issue_wv_tile(smh, tid, 1);

#pragma unroll
        for (int mt = 0; mt < 2; mt++) {
#pragma unroll
            for (int nt = 0; nt < 2; nt++) {
                int dcol = wn * 16 + nt * 8 + 2 * c;
                float b0 = bk[dcol], b1 = bk[dcol + 1];
                size_t r0 = ((size_t)b * HWn + p0 + wm * 32 + mt * 16 + g) * 64 + dcol;
                size_t r1 = r0 + (size_t)8 * 64;
                __half h0, l0, h1, l1;
                split2(acc[mt][nt][0] + b0, h0, l0);
                split2(acc[mt][nt][1] + b1, h1, l1);
                *(uint32_t*)&g_kh[r0] = pack2(h0, h1);
                *(uint32_t*)&g_kl[r0] = pack2(l0, l1);
                split2(acc[mt][nt][2] + b0, h0, l0);
                split2(acc[mt][nt][3] + b1, h1, l1);
                *(uint32_t*)&g_kh[r1] = pack2(h0, h1);
                *(uint32_t*)&g_kl[r1] = pack2(l0, l1);
            }
        }
    }

    // ---- Phase B: v = X_hi * Wv^T (1-term), double-buffered Wv tiles ----
    for (int oh = 0; oh < 2; oh++) {
        float acc[2][4][4] = {};
        for (int kc = 0; kc < 4; kc++) {
            int t = oh * 4 + kc;
            if (t < 7) CPWAIT(1); else CPWAIT(0);
            __syncthreads();
            const __half* wb = smh + 67584 + (t & 1) * 9216;
#pragma unroll
            for (int kt = 0; kt < 4; kt++) {
                int k0 = kc * 64 + kt * 16;
                uint32_t a0[4], a1[4];
                ldmA(a0, xh, wm * 32, k0, lane, PSV);
                ldmA(a1, xh, wm * 32 + 16, k0, lane, PSV);
#pragma unroll
                for (int ntp = 0; ntp < 2; ntp++) {
                    uint32_t bb[4];
                    ldmB2(bb, wb, wn * 32 + ntp * 16, kt * 16, lane, PS);
                    mma16816(acc[0][2 * ntp], a0, bb);
                    mma16816(acc[1][2 * ntp], a1, bb);
                    mma16816(acc[0][2 * ntp + 1], a0, bb + 2);
                    mma16816(acc[1][2 * ntp + 1], a1, bb + 2);
                }
            }
            __syncthreads();
            if (t + 2 <= 7) issue_wv_tile(smh, tid, t + 2);
        }
#pragma unroll
        for (int mt = 0; mt < 2; mt++) {
#pragma unroll
            for (int nt = 0; nt < 4; nt++) {
                int o = oh * 128 + wn * 32 + nt * 8 + 2 * c;
                int p = p0 + wm * 32 + mt * 16 + g;
                float b0 = bv[o], b1 = bv[o + 1];
                g_v[(size_t)(b * 256 + o) * HWn + p]         = __float2half_rn(acc[mt][nt][0] + b0);
                g_v[(size_t)(b * 256 + o + 1) * HWn + p]     = __float2half_rn(acc[mt][nt][1] + b1);
                g_v[(size_t)(b * 256 + o) * HWn + p + 8]     = __float2half_rn(acc[mt][nt][2] + b0);
                g_v[(size_t)(b * 256 + o + 1) * HWn + p + 8] = __float2half_rn(acc[mt][nt][3] + b1);
            }
        }
    }
}

// ---------------------------------------------------------------------------
// Fused attention per (qt, h, b): E (3-term) -> warp softmax -> AV (1-term).
// Unchanged (known-good).
// ---------------------------------------------------------------------------
#define A_SMEM (110592 + 67584)
__global__ __launch_bounds__(256, 1) void attn(float* __restrict__ out)
{
    extern __shared__ __half smh[];
    __half* qh = smh;
    __half* ql = qh + 128 * PS;
    __half* kh = ql + 128 * PS;
    __half* kl = kh + 256 * PS;
    __half* vs0 = smh + 55296;
    __half* vs1 = smh;

    const int tid = threadIdx.x, w = tid >> 5, lane = tid & 31;
    const int c = lane & 3, g = lane >> 2;
    const int qt = blockIdx.x, h = blockIdx.y, b = blockIdx.z;
    const int w0 = qt * 128;
    const __half* vg = g_v + (size_t)b * 256 * HWn + h * Wn;

    {
        const __half* qsh = g_qh + ((size_t)b * HWn + h * Wn + w0) * 64;
        const __half* qsl = g_ql + ((size_t)b * HWn + h * Wn + w0) * 64;
        const __half* ksh = g_kh + ((size_t)b * HWn + h * Wn) * 64;
        const __half* ksl = g_kl + ((size_t)b * HWn + h * Wn) * 64;
        for (int i = tid; i < 1024; i += 256) {
            int r = i >> 3, s = (i & 7) * 8;
            CP16(sptr(qh + r * PS + s), qsh + r * 64 + s);
            CP16(sptr(ql + r * PS + s), qsl + r * 64 + s);
        }
        for (int i = tid; i < 2048; i += 256) {
            int r = i >> 3, s = (i & 7) * 8;
            CP16(sptr(kh + r * PS + s), ksh + r * 64 + s);
            CP16(sptr(kl + r * PS + s), ksl + r * 64 + s);
        }
        CPCOMMIT();
    }
    for (int i = tid; i < 4096; i += 256) {
        int o = i >> 5, s = (i & 31) * 8;
        CP16(sptr(vs0 + o * PSV + s), vg + (size_t)o * HWn + s);
    }
    CPCOMMIT();

    CPWAIT(1);
    __syncthreads();

    float e[32][4] = {};
#pragma unroll
    for (int kt = 0; kt < 4; kt++) {
        uint32_t ah[4], al[4];
        ldmA(ah, qh, w * 16, kt * 16, lane, PS);
        ldmA(al, ql, w * 16, kt * 16, lane, PS);
#pragma unroll
        for (int nt = 0; nt < 32; nt += 2) {
            uint32_t bh[4], bl[4];
            ldmB2(bh, kh, nt * 8, kt * 16, lane, PS);
            ldmB2(bl, kl, nt * 8, kt * 16, lane, PS);
            mma16816(e[nt], ah, bh);
            mma16816(e[nt], ah, bl);
            mma16816(e[nt], al, bh);
            mma16816(e[nt + 1], ah, bh + 2);
            mma16816(e[nt + 1], ah, bl + 2);
            mma16816(e[nt + 1], al, bh + 2);
        }
    }
    __syncthreads();

    for (int i = tid; i < 4096; i += 256) {
        int o = i >> 5, s = (i & 31) * 8;
        CP16(sptr(vs1 + o * PSV + s), vg + (size_t)(o + 128) * HWn + s);
    }
    CPCOMMIT();

    float m0 = -1e30f, m1 = -1e30f;
#pragma unroll
    for (int nt = 0; nt < 32; nt++) {
        m0 = fmaxf(m0, fmaxf(e[nt][0], e[nt][1]));
        m1 = fmaxf(m1, fmaxf(e[nt][2], e[nt][3]));
    }
    m0 = fmaxf(m0, __shfl_xor_sync(0xffffffffu, m0, 1));
    m0 = fmaxf(m0, __shfl_xor_sync(0xffffffffu, m0, 2));
    m1 = fmaxf(m1, __shfl_xor_sync(0xffffffffu, m1, 1));
    m1 = fmaxf(m1, __shfl_xor_sync(0xffffffffu, m1, 2));

    float s0 = 0.f, s1 = 0.f;
    uint32_t ah_[64];
#pragma unroll
    for (int nt = 0; nt < 32; nt++) {
        float p00 = __expf(e[nt][0] - m0), p01 = __expf(e[nt][1] - m0);
        float p10 = __expf(e[nt][2] - m1), p11 = __expf(e[nt][3] - m1);
        s0 += p00 + p01;
        s1 += p10 + p11;
        ah_[2 * nt]     = pack2(__float2half_rn(p00), __float2half_rn(p01));
        ah_[2 * nt + 1] = pack2(__float2half_rn(p10), __float2half_rn(p11));
    }
    s0 += __shfl_xor_sync(0xffffffffu, s0, 1);
    s0 += __shfl_xor_sync(0xffffffffu, s0, 2);
    s1 += __shfl_xor_sync(0xffffffffu, s1, 1);
    s1 += __shfl_xor_sync(0xffffffffu, s1, 2);
    const float rinv0 = 1.0f / s0, rinv1 = 1.0f / s1;

    CPWAIT(1);
    __syncthreads();
    {
        float oacc[16][4] = {};
#pragma unroll
        for (int kt = 0; kt < 16; kt++) {
            const uint32_t* Ah = &ah_[4 * kt];
#pragma unroll
            for (int nt = 0; nt < 16; nt += 2) {
                uint32_t bb[4];
                ldmB2(bb, vs0, nt * 8, kt * 16, lane, PSV);
                mma16816(oacc[nt], Ah, bb);
                mma16816(oacc[nt + 1], Ah, bb + 2);
            }
        }
#pragma unroll
        for (int nt = 0; nt < 16; nt++) {
            int o = nt * 8 + 2 * c;
            size_t i0 = (size_t)(b * 256 + o) * HWn + h * Wn + w0 + w * 16 + g;
            out[i0]           = oacc[nt][0] * rinv0;
            out[i0 + HWn]     = oacc[nt][1] * rinv0;
            out[i0 + 8]       = oacc[nt][2] * rinv1;
            out[i0 + HWn + 8] = oacc[nt][3] * rinv1;
        }
    }

    CPWAIT(0);
    __syncthreads();
    {
        float oacc[16][4] = {};
#pragma unroll
        for (int kt = 0; kt < 16; kt++) {
            const uint32_t* Ah = &ah_[4 * kt];
#pragma unroll
            for (int nt = 0; nt < 16; nt += 2) {
                uint32_t bb[4];
                ldmB2(bb, vs1, nt * 8, kt * 16, lane, PSV);
                mma16816(oacc[nt], Ah, bb);
                mma16816(oacc[nt + 1], Ah, bb + 2);
            }
        }
#pragma unroll
        for (int nt = 0; nt < 16; nt++) {
            int o = 128 + nt * 8 + 2 * c;
            size_t i0 = (size_t)(b * 256 + o) * HWn + h * Wn + w0 + w * 16 + g;
            out[i0]           = oacc[nt][0] * rinv0;
            out[i0 + HWn]     = oacc[nt][1] * rinv0;
            out[i0 + 8]       = oacc[nt][2] * rinv1;
            out[i0 + HWn + 8] = oacc[nt][3] * rinv1;
        }
    }
}

// ---------------------------------------------------------------------------
extern "C" void kernel_launch(void* const* d_in, const int* in_sizes, int n_in,
                              void* d_out, int out_size)
{
    const float* flow   = (const float*)d_in[0];
    const float* de_out = (const float*)d_in[1];
    const float* Wq     = (const float*)d_in[2];
    const float* bq     = (const float*)d_in[3];
    const float* Wk     = (const float*)d_in[4];
    const float* bk     = (const float*)d_in[5];
    const float* Wv     = (const float*)d_in[6];
    const float* bv     = (const float*)d_in[7];
    float* out = (float*)d_out;

    cudaFuncSetAttribute(q_proj,  cudaFuncAttributeMaxDynamicSharedMemorySize, Q_SMEM);
    cudaFuncSetAttribute(kv_proj, cudaFuncAttributeMaxDynamicSharedMemorySize, KV_SMEM);
    cudaFuncSetAttribute(attn,    cudaFuncAttributeMaxDynamicSharedMemorySize, A_SMEM);

    prep<<<192, 256>>>(Wq, Wk, Wv);
    q_proj<<<dim3(HWn / 128, 1, Bn), 256, Q_SMEM>>>(de_out, bq);
    kv_proj<<<dim3(HWn / 128, 1, Bn), 512, KV_SMEM>>>(flow, bk, bv);
    attn<<<dim3(Wn / 128, Hn, Bn), 256, A_SMEM>>>(out);
}

// round 12
// speedup vs baseline: 1.1081x; 1.1081x over previous
#include <cuda_runtime.h>
#include <cuda_fp16.h>
#include <cstdint>

#define Bn 4
#define Cn 256
#define Hn 128
#define Wn 256
#define HWn 32768
#define PS 72    // smem stride (halves), 64-wide tiles
#define PSV 264  // smem stride (halves), 256-wide rows

// q,k pre-split hi/lo fp16 [b][p][64]; v plain fp16 [b][o][p]
__device__ __half g_qh[(size_t)Bn * HWn * 64];
__device__ __half g_ql[(size_t)Bn * HWn * 64];
__device__ __half g_kh[(size_t)Bn * HWn * 64];
__device__ __half g_kl[(size_t)Bn * HWn * 64];
__device__ __half g_v [(size_t)Bn * 256 * HWn];
// pre-converted weights
__device__ __half g_wqh[64 * 256], g_wql[64 * 256];
__device__ __half g_wkh[64 * 256], g_wkl[64 * 256];
__device__ __half g_wv16[256 * 256];

// ---------------- helpers ----------------
static __device__ __forceinline__ void split2(float x, __half& h, __half& l) {
    h = __float2half_rn(x);
    l = __float2half_rn(x - __half2float(h));
}
static __device__ __forceinline__ uint32_t pack2(__half a, __half b) {
    __half2 t = __halves2half2(a, b);
    return *(uint32_t*)&t;
}
static __device__ __forceinline__ uint32_t sptr(const void* p) {
    return (uint32_t)__cvta_generic_to_shared(p);
}
static __device__ __forceinline__ void mma16816(float* d, const uint32_t* a, const uint32_t* b) {
    asm volatile("mma.sync.aligned.m16n8k16.row.col.f32.f16.f16.f32 "
        "{%0,%1,%2,%3}, {%4,%5,%6,%7}, {%8,%9}, {%0,%1,%2,%3};"
        : "+f"(d[0]), "+f"(d[1]), "+f"(d[2]), "+f"(d[3])
        : "r"(a[0]), "r"(a[1]), "r"(a[2]), "r"(a[3]), "r"(b[0]), "r"(b[1]));
}
static __device__ __forceinline__ void ldmA(uint32_t* a, const __half* t, int m0, int k0,
                                            int lane, int stride) {
    const __half* p = t + (m0 + (lane & 15)) * stride + k0 + ((lane >> 4) << 3);
    asm volatile("ldmatrix.sync.aligned.m8n8.x4.shared.b16 {%0,%1,%2,%3}, [%4];"
        : "=r"(a[0]), "=r"(a[1]), "=r"(a[2]), "=r"(a[3]) : "r"(sptr(p)));
}
static __device__ __forceinline__ void ldmB2(uint32_t* b, const __half* t, int n0, int k0,
                                             int lane, int stride) {
    int grp = lane >> 3;
    const __half* p = t + (n0 + ((grp & 2) << 2) + (lane & 7)) * stride + k0 + ((grp & 1) << 3);
    asm volatile("ldmatrix.sync.aligned.m8n8.x4.shared.b16 {%0,%1,%2,%3}, [%4];"
        : "=r"(b[0]), "=r"(b[1]), "=r"(b[2]), "=r"(b[3]) : "r"(sptr(p)));
}
#define CP16(d, s)  asm volatile("cp.async.cg.shared.global [%0], [%1], 16;" :: "r"(d), "l"(s))
#define CPCOMMIT()  asm volatile("cp.async.commit_group;")
#define CPWAIT(n)   asm volatile("cp.async.wait_group %0;" :: "n"(n) : "memory")

// ---------------------------------------------------------------------------
// prep: Wq/Wk -> hi/lo fp16, Wv -> fp16
// ---------------------------------------------------------------------------
__global__ void prep(const float* __restrict__ Wq, const float* __restrict__ Wk,
                     const float* __restrict__ Wv)
{
    int i = (blockIdx.x * 256 + threadIdx.x) * 2;
    __half h0, l0, h1, l1;
    if (i < 16384) {
        split2(Wq[i], h0, l0); split2(Wq[i + 1], h1, l1);
        *(uint32_t*)&g_wqh[i] = pack2(h0, h1);
        *(uint32_t*)&g_wql[i] = pack2(l0, l1);
    } else if (i < 32768) {
        int j = i - 16384;
        split2(Wk[j], h0, l0); split2(Wk[j + 1], h1, l1);
        *(uint32_t*)&g_wkh[j] = pack2(h0, h1);
        *(uint32_t*)&g_wkl[j] = pack2(l0, l1);
    } else {
        int j = i - 32768;
        *(uint32_t*)&g_wv16[j] = pack2(__float2half_rn(Wv[j]), __float2half_rn(Wv[j + 1]));
    }
}

// ---------------------------------------------------------------------------
// q/k projection (3-term split): D[128 p, 64 d] = X^T * W^T + bias
// grid (HWn/128, 2, B), 256 threads. (R10 proven version)
// ---------------------------------------------------------------------------
#define QK_SMEM 73728
__global__ __launch_bounds__(256) void qk_proj(
    const float* __restrict__ de_out, const float* __restrict__ flow,
    const float* __restrict__ bq, const float* __restrict__ bk)
{
    extern __shared__ __half smh[];
    __half* xh = smh;
    __half* xl = smh + 9216;

    const int tid = threadIdx.x, w = tid >> 5, lane = tid & 31;
    const int c = lane & 3, g = lane >> 2;
    const int wm = w & 3, wn = w >> 2;
    const int p0 = blockIdx.x * 128, isK = blockIdx.y, b = blockIdx.z;

    const float*  X    = isK ? flow : de_out;
    const float*  bias = isK ? bk : bq;
    const __half* wsh  = isK ? g_wkh : g_wqh;
    const __half* wsl  = isK ? g_wkl : g_wql;
    __half*       Yh   = isK ? g_kh : g_qh;
    __half*       Yl   = isK ? g_kl : g_ql;
    const float* Xb = X + (size_t)b * Cn * HWn;

    float acc[2][4][4] = {};

    {
        __half* wb = smh + 18432;
        for (int i = tid; i < 512; i += 256) {
            int d = i >> 3, s = (i & 7) * 8;
            CP16(sptr(wb + d * PS + s), wsh + d * 256 + s);
            CP16(sptr(wb + 4608 + d * PS + s), wsl + d * 256 + s);
        }
        CPCOMMIT();
    }

    for (int kc = 0; kc < 4; kc++) {
        if (kc < 3) {
            __half* wb = smh + 18432 + ((kc + 1) & 1) * 9216;
            for (int i = tid; i < 512; i += 256) {
                int d = i >> 3, s = (i & 7) * 8;
                CP16(sptr(wb + d * PS + s), wsh + d * 256 + (kc + 1) * 64 + s);
                CP16(sptr(wb + 4608 + d * PS + s), wsl + d * 256 + (kc + 1) * 64 + s);
            }
            CPCOMMIT();
        }
        for (int i = tid; i < 2048; i += 256) {
            int p = i & 127, cg = i >> 7;
            const float* src = &Xb[(size_t)(kc * 64 + cg * 4) * HWn + p0 + p];
            __half h0, l0, h1, l1;
            uint2 hv, lv;
            split2(src[0], h0, l0);
            split2(src[(size_t)HWn], h1, l1);
            hv.x = pack2(h0, h1); lv.x = pack2(l0, l1);
            split2(src[2 * (size_t)HWn], h0, l0);
            split2(src[3 * (size_t)HWn], h1, l1);
            hv.y = pack2(h0, h1); lv.y = pack2(l0, l1);
            *(uint2*)&xh[p * PS + cg * 4] = hv;
            *(uint2*)&xl[p * PS + cg * 4] = lv;
        }
        if (kc < 3) CPWAIT(1); else CPWAIT(0);
        __syncthreads();

        const __half* wh = smh + 18432 + (kc & 1) * 9216;
        const __half* wl = wh + 4608;
#pragma unroll
        for (int kt = 0; kt < 4; kt++) {
            uint32_t ah0[4], al0[4], ah1[4], al1[4];
            ldmA(ah0, xh, wm * 32, kt * 16, lane, PS);
            ldmA(al0, xl, wm * 32, kt * 16, lane, PS);
            ldmA(ah1, xh, wm * 32 + 16, kt * 16, lane, PS);
            ldmA(al1, xl, wm * 32 + 16, kt * 16, lane, PS);
#pragma unroll
            for (int nt = 0; nt < 4; nt += 2) {
                uint32_t bh[4], bl[4];
                ldmB2(bh, wh, wn * 32 + nt * 8, kt * 16, lane, PS);
                ldmB2(bl, wl, wn * 32 + nt * 8, kt * 16, lane, PS);
                mma16816(acc[0][nt], ah0, bh);
                mma16816(acc[0][nt], ah0, bl);
                mma16816(acc[0][nt], al0, bh);
                mma16816(acc[1][nt], ah1, bh);
                mma16816(acc[1][nt], ah1, bl);
                mma16816(acc[1][nt], al1, bh);
                mma16816(acc[0][nt + 1], ah0, bh + 2);
                mma16816(acc[0][nt + 1], ah0, bl + 2);
                mma16816(acc[0][nt + 1], al0, bh + 2);
                mma16816(acc[1][nt + 1], ah1, bh + 2);
                mma16816(acc[1][nt + 1], ah1, bl + 2);
                mma16816(acc[1][nt + 1], al1, bh + 2);
            }
        }
        __syncthreads();
    }
#pragma unroll
    for (int mt = 0; mt < 2; mt++) {
#pragma unroll
        for (int nt = 0; nt < 4; nt++) {
            int dcol = wn * 32 + nt * 8 + 2 * c;
            float b0 = bias[dcol], b1 = bias[dcol + 1];
            size_t r0 = ((size_t)b * HWn + p0 + wm * 32 + mt * 16 + g) * 64 + dcol;
            size_t r1 = r0 + (size_t)8 * 64;
            __half h0, l0, h1, l1;
            split2(acc[mt][nt][0] + b0, h0, l0);
            split2(acc[mt][nt][1] + b1, h1, l1);
            *(uint32_t*)&Yh[r0] = pack2(h0, h1);
            *(uint32_t*)&Yl[r0] = pack2(l0, l1);
            split2(acc[mt][nt][2] + b0, h0, l0);
            split2(acc[mt][nt][3] + b1, h1, l1);
            *(uint32_t*)&Yh[r1] = pack2(h0, h1);
            *(uint32_t*)&Yl[r1] = pack2(l0, l1);
        }
    }
}

// ---------------------------------------------------------------------------
// v projection (1-term): D[128 p, 256 o] -> g_v fp16 [b][o][p]
// grid (HWn/128, 1, B), 256 threads, 2 blocks/SM. (R10 proven version)
// ---------------------------------------------------------------------------
#define V_SMEM (67584 + 2 * 18432)
static __device__ __forceinline__ void issue_wv_tile(__half* smh, int tid, int t) {
    __half* wb = smh + 33792 + (t & 1) * 9216;
    int oh = t >> 2, kc = t & 3;
    for (int i = tid; i < 1024; i += 256) {
        int o = i >> 3, s = (i & 7) * 8;
        CP16(sptr(wb + o * PS + s), g_wv16 + (size_t)(oh * 128 + o) * 256 + kc * 64 + s);
    }
    CPCOMMIT();
}
__global__ __launch_bounds__(256, 2) void v_proj(
    const float* __restrict__ flow, const float* __restrict__ bv)
{
    extern __shared__ __half smh[];
    __half* xs = smh;   // [128][264]

    const int tid = threadIdx.x, w = tid >> 5, lane = tid & 31;
    const int c = lane & 3, g = lane >> 2;
    const int wm = w & 3, wn = w >> 2;
    const int p0 = blockIdx.x * 128, b = blockIdx.z;
    const float* Xb = flow + (size_t)b * Cn * HWn;

    issue_wv_tile(smh, tid, 0);
    issue_wv_tile(smh, tid, 1);

    for (int i = tid; i < 8192; i += 256) {
        int p = i & 127, cg = i >> 7;
        const float* src = &Xb[(size_t)(cg * 4) * HWn + p0 + p];
        uint2 hv;
        hv.x = pack2(__float2half_rn(src[0]), __float2half_rn(src[(size_t)HWn]));
        hv.y = pack2(__float2half_rn(src[2 * (size_t)HWn]), __float2half_rn(src[3 * (size_t)HWn]));
        *(uint2*)&xs[p * PSV + cg * 4] = hv;
    }
    __syncthreads();

    for (int oh = 0; oh < 2; oh++) {
        float acc[2][8][4] = {};
        for (int kc = 0; kc < 4; kc++) {
            int t = oh * 4 + kc;
            if (t < 7) CPWAIT(1); else CPWAIT(0);
            __syncthreads();
            const __half* wb = smh + 33792 + (t & 1) * 9216;
#pragma unroll
            for (int ktc = 0; ktc < 4; ktc++) {
                uint32_t a0[4], a1[4];
                ldmA(a0, xs, wm * 32, kc * 64 + ktc * 16, lane, PSV);
                ldmA(a1, xs, wm * 32 + 16, kc * 64 + ktc * 16, lane, PSV);
#pragma unroll
                for (int ntp = 0; ntp < 4; ntp++) {
                    uint32_t bb[4];
                    ldmB2(bb, wb, wn * 64 + ntp * 16, ktc * 16, lane, PS);
                    mma16816(acc[0][2 * ntp], a0, bb);
                    mma16816(acc[1][2 * ntp], a1, bb);
                    mma16816(acc[0][2 * ntp + 1], a0, bb + 2);
                    mma16816(acc[1][2 * ntp + 1], a1, bb + 2);
                }
            }
            __syncthreads();
            if (t + 2 <= 7) issue_wv_tile(smh, tid, t + 2);
        }
#pragma unroll
        for (int mt = 0; mt < 2; mt++) {
#pragma unroll
            for (int nt = 0; nt < 8; nt++) {
                int o = oh * 128 + wn * 64 + nt * 8 + 2 * c;
                int p = p0 + wm * 32 + mt * 16 + g;
                float b0 = bv[o], b1 = bv[o + 1];
                g_v[(size_t)(b * 256 + o) * HWn + p]         = __float2half_rn(acc[mt][nt][0] + b0);
                g_v[(size_t)(b * 256 + o + 1) * HWn + p]     = __float2half_rn(acc[mt][nt][1] + b1);
                g_v[(size_t)(b * 256 + o) * HWn + p + 8]     = __float2half_rn(acc[mt][nt][2] + b0);
                g_v[(size_t)(b * 256 + o + 1) * HWn + p + 8] = __float2half_rn(acc[mt][nt][3] + b1);
            }
        }
    }
}

// ---------------------------------------------------------------------------
// Fused attention v2: 512 threads, 16 warps = 8 q-groups x 2 key-halves.
// E (3-term, per-warp 16q x 128k) -> cross-warp softmax (static smem red) ->
// att fp16 to smem -> AV (1-term, warp = 16q x 64o per chunk).
// smem (halves): q 0..18432 | k 18432..55296 | [after E: att 0..33792,
// vs1 33792..67584] | vs0 67584..101376.  Total 202752 B.
// ---------------------------------------------------------------------------
#define A_SMEM 202752
__global__ __launch_bounds__(512, 1) void attn(float* __restrict__ out)
{
    extern __shared__ __half smh[];
    __half* qh  = smh;
    __half* ql  = smh + 9216;
    __half* kh  = smh + 18432;
    __half* kl  = smh + 36864;
    __half* att = smh;             // [128 q][264] fp16, alias after E
    __half* vs1 = smh + 33792;     // [128 o][264], alias after E
    __half* vs0 = smh + 67584;     // [128 o][264]
    __shared__ float redmax[2][128];
    __shared__ float redsum[2][128];

    const int tid = threadIdx.x, w = tid >> 5, lane = tid & 31;
    const int c = lane & 3, g = lane >> 2;
    const int wq = w >> 1, wk = w & 1;
    const int qt = blockIdx.x, h = blockIdx.y, b = blockIdx.z;
    const int w0 = qt * 128;
    const int row0 = wq * 16 + g, row1 = wq * 16 + 8 + g;
    const __half* vg = g_v + (size_t)b * 256 * HWn + h * Wn;

    // group 0: q/k hi+lo; group 1: vs0 (overlaps E)
    {
        const __half* qsh = g_qh + ((size_t)b * HWn + h * Wn + w0) * 64;
        const __half* qsl = g_ql + ((size_t)b * HWn + h * Wn + w0) * 64;
        const __half* ksh = g_kh + ((size_t)b * HWn + h * Wn) * 64;
        const __half* ksl = g_kl + ((size_t)b * HWn + h * Wn) * 64;
        for (int i = tid; i < 1024; i += 512) {
            int r = i >> 3, s = (i & 7) * 8;
            CP16(sptr(qh + r * PS + s), qsh + r * 64 + s);
            CP16(sptr(ql + r * PS + s), qsl + r * 64 + s);
        }
        for (int i = tid; i < 2048; i += 512) {
            int r = i >> 3, s = (i & 7) * 8;
            CP16(sptr(kh + r * PS + s), ksh + r * 64 + s);
            CP16(sptr(kl + r * PS + s), ksl + r * 64 + s);
        }
        CPCOMMIT();
    }
    for (int i = tid; i < 4096; i += 512) {
        int o = i >> 5, s = (i & 31) * 8;
        CP16(sptr(vs0 + o * PSV + s), vg + (size_t)o * HWn + s);
    }
    CPCOMMIT();

    CPWAIT(1);
    __syncthreads();

    // E: warp rows wq*16..+16, keys wk*128..+128 (3-term split)
    float e[16][4] = {};
#pragma unroll
    for (int kt = 0; kt < 4; kt++) {
        uint32_t ah[4], al[4];
        ldmA(ah, qh, wq * 16, kt * 16, lane, PS);
        ldmA(al, ql, wq * 16, kt * 16, lane, PS);
#pragma unroll
        for (int nt = 0; nt < 16; nt += 2) {
            uint32_t bh[4], bl[4];
            ldmB2(bh, kh, wk * 128 + nt * 8, kt * 16, lane, PS);
            ldmB2(bl, kl, wk * 128 + nt * 8, kt * 16, lane, PS);
            mma16816(e[nt], ah, bh);
            mma16816(e[nt], ah, bl);
            mma16816(e[nt], al, bh);
            mma16816(e[nt + 1], ah, bh + 2);
            mma16816(e[nt + 1], ah, bl + 2);
            mma16816(e[nt + 1], al, bh + 2);
        }
    }

    // local max over this key half
    float m0 = -1e30f, m1 = -1e30f;
#pragma unroll
    for (int nt = 0; nt < 16; nt++) {
        m0 = fmaxf(m0, fmaxf(e[nt][0], e[nt][1]));
        m1 = fmaxf(m1, fmaxf(e[nt][2], e[nt][3]));
    }
    m0 = fmaxf(m0, __shfl_xor_sync(0xffffffffu, m0, 1));
    m0 = fmaxf(m0, __shfl_xor_sync(0xffffffffu, m0, 2));
    m1 = fmaxf(m1, __shfl_xor_sync(0xffffffffu, m1, 1));
    m1 = fmaxf(m1, __shfl_xor_sync(0xffffffffu, m1, 2));
    if (c == 0) {
        redmax[wk][row0] = m0;
        redmax[wk][row1] = m1;
    }
    __syncthreads();   // q/k reads done + redmax visible

    // issue vs1 into aliased k region (overlaps softmax + AV chunk0)
    for (int i = tid; i < 4096; i += 512) {
        int o = i >> 5, s = (i & 31) * 8;
        CP16(sptr(vs1 + o * PSV + s), vg + (size_t)(o + 128) * HWn + s);
    }
    CPCOMMIT();

    // combined max, exp, att write, sum
    m0 = fmaxf(redmax[0][row0], redmax[1][row0]);
    m1 = fmaxf(redmax[0][row1], redmax[1][row1]);
    float s0 = 0.f, s1 = 0.f;
    uint32_t* att32 = (uint32_t*)att;
#pragma unroll
    for (int nt = 0; nt < 16; nt++) {
        float p00 = __expf(e[nt][0] - m0), p01 = __expf(e[nt][1] - m0);
        float p10 = __expf(e[nt][2] - m1), p11 = __expf(e[nt][3] - m1);
        s0 += p00 + p01;
        s1 += p10 + p11;
        int cw = (wk * 128 + nt * 8 + 2 * c) >> 1;
        att32[row0 * 132 + cw] = pack2(__float2half_rn(p00), __float2half_rn(p01));
        att32[row1 * 132 + cw] = pack2(__float2half_rn(p10), __float2half_rn(p11));
    }
    s0 += __shfl_xor_sync(0xffffffffu, s0, 1);
    s0 += __shfl_xor_sync(0xffffffffu, s0, 2);
    s1 += __shfl_xor_sync(0xffffffffu, s1, 1);
    s1 += __shfl_xor_sync(0xffffffffu, s1, 2);
    if (c == 0) {
        redsum[wk][row0] = s0;
        redsum[wk][row1] = s1;
    }
    CPWAIT(1);        // vs0 arrived (vs1 still in flight)
    __syncthreads();  // att + redsum + vs0 visible

    const float rinv0 = 1.0f / (redsum[0][row0] + redsum[1][row0]);
    const float rinv1 = 1.0f / (redsum[0][row1] + redsum[1][row1]);

    // AV: warp = rows wq*16, o = ch*128 + wk*64 .. +64, K = 256
    for (int ch = 0; ch < 2; ch++) {
        if (ch) { CPWAIT(0); __syncthreads(); }
        const __half* vs = ch ? vs1 : vs0;
        float oacc[8][4] = {};
#pragma unroll
        for (int kt = 0; kt < 16; kt++) {
            uint32_t aa[4];
            ldmA(aa, att, wq * 16, kt * 16, lane, PSV);
#pragma unroll
            for (int ntp = 0; ntp < 4; ntp++) {
                uint32_t bb[4];
                ldmB2(bb, vs, wk * 64 + ntp * 16, kt * 16, lane, PSV);
                mma16816(oacc[2 * ntp], aa, bb);
                mma16816(oacc[2 * ntp + 1], aa, bb + 2);
            }
        }
#pragma unroll
        for (int nt = 0; nt < 8; nt++) {
            int o = ch * 128 + wk * 64 + nt * 8 + 2 * c;
            size_t i0 = (size_t)(b * 256 + o) * HWn + h * Wn + w0 + wq * 16 + g;
            out[i0]           = oacc[nt][0] * rinv0;
            out[i0 + HWn]     = oacc[nt][1] * rinv0;
            out[i0 + 8]       = oacc[nt][2] * rinv1;
            out[i0 + HWn + 8] = oacc[nt][3] * rinv1;
        }
    }
}

// ---------------------------------------------------------------------------
extern "C" void kernel_launch(void* const* d_in, const int* in_sizes, int n_in,
                              void* d_out, int out_size)
{
    const float* flow   = (const float*)d_in[0];
    const float* de_out = (const float*)d_in[1];
    const float* Wq     = (const float*)d_in[2];
    const float* bq     = (const float*)d_in[3];
    const float* Wk     = (const float*)d_in[4];
    const float* bk     = (const float*)d_in[5];
    const float* Wv     = (const float*)d_in[6];
    const float* bv     = (const float*)d_in[7];
    float* out = (float*)d_out;

    cudaFuncSetAttribute(qk_proj, cudaFuncAttributeMaxDynamicSharedMemorySize, QK_SMEM);
    cudaFuncSetAttribute(v_proj,  cudaFuncAttributeMaxDynamicSharedMemorySize, V_SMEM);
    cudaFuncSetAttribute(attn,    cudaFuncAttributeMaxDynamicSharedMemorySize, A_SMEM);

    prep<<<192, 256>>>(Wq, Wk, Wv);
    qk_proj<<<dim3(HWn / 128, 2, Bn), 256, QK_SMEM>>>(de_out, flow, bq, bk);
    v_proj<<<dim3(HWn / 128, 1, Bn), 256, V_SMEM>>>(flow, bv);
    attn<<<dim3(Wn / 128, Hn, Bn), 512, A_SMEM>>>(out);
}

// round 13
// speedup vs baseline: 1.1117x; 1.0033x over previous
#include <cuda_runtime.h>
#include <cuda_fp16.h>
#include <cstdint>

#define Bn 4
#define Cn 256
#define Hn 128
#define Wn 256
#define HWn 32768
#define PS 72    // smem stride (halves), 64-wide tiles
#define PSV 264  // smem stride (halves), 256-wide rows

// q,k pre-split hi/lo fp16 [b][p][64]; v plain fp16 [b][o][p]
__device__ __half g_qh[(size_t)Bn * HWn * 64];
__device__ __half g_ql[(size_t)Bn * HWn * 64];
__device__ __half g_kh[(size_t)Bn * HWn * 64];
__device__ __half g_kl[(size_t)Bn * HWn * 64];
__device__ __half g_v [(size_t)Bn * 256 * HWn];
// pre-converted weights
__device__ __half g_wqh[64 * 256], g_wql[64 * 256];
__device__ __half g_wkh[64 * 256], g_wkl[64 * 256];
__device__ __half g_wv16[256 * 256];

// ---------------- helpers ----------------
static __device__ __forceinline__ void split2(float x, __half& h, __half& l) {
    h = __float2half_rn(x);
    l = __float2half_rn(x - __half2float(h));
}
static __device__ __forceinline__ uint32_t pack2(__half a, __half b) {
    __half2 t = __halves2half2(a, b);
    return *(uint32_t*)&t;
}
static __device__ __forceinline__ uint32_t sptr(const void* p) {
    return (uint32_t)__cvta_generic_to_shared(p);
}
static __device__ __forceinline__ void mma16816(float* d, const uint32_t* a, const uint32_t* b) {
    asm volatile("mma.sync.aligned.m16n8k16.row.col.f32.f16.f16.f32 "
        "{%0,%1,%2,%3}, {%4,%5,%6,%7}, {%8,%9}, {%0,%1,%2,%3};"
        : "+f"(d[0]), "+f"(d[1]), "+f"(d[2]), "+f"(d[3])
        : "r"(a[0]), "r"(a[1]), "r"(a[2]), "r"(a[3]), "r"(b[0]), "r"(b[1]));
}
static __device__ __forceinline__ void ldmA(uint32_t* a, const __half* t, int m0, int k0,
                                            int lane, int stride) {
    const __half* p = t + (m0 + (lane & 15)) * stride + k0 + ((lane >> 4) << 3);
    asm volatile("ldmatrix.sync.aligned.m8n8.x4.shared.b16 {%0,%1,%2,%3}, [%4];"
        : "=r"(a[0]), "=r"(a[1]), "=r"(a[2]), "=r"(a[3]) : "r"(sptr(p)));
}
static __device__ __forceinline__ void ldmB2(uint32_t* b, const __half* t, int n0, int k0,
                                             int lane, int stride) {
    int grp = lane >> 3;
    const __half* p = t + (n0 + ((grp & 2) << 2) + (lane & 7)) * stride + k0 + ((grp & 1) << 3);
    asm volatile("ldmatrix.sync.aligned.m8n8.x4.shared.b16 {%0,%1,%2,%3}, [%4];"
        : "=r"(b[0]), "=r"(b[1]), "=r"(b[2]), "=r"(b[3]) : "r"(sptr(p)));
}
#define CP16(d, s)  asm volatile("cp.async.cg.shared.global [%0], [%1], 16;" :: "r"(d), "l"(s))
#define CPCOMMIT()  asm volatile("cp.async.commit_group;")
#define CPWAIT(n)   asm volatile("cp.async.wait_group %0;" :: "n"(n) : "memory")

// ---------------------------------------------------------------------------
// prep: Wq/Wk -> hi/lo fp16, Wv -> fp16
// ---------------------------------------------------------------------------
__global__ void prep(const float* __restrict__ Wq, const float* __restrict__ Wk,
                     const float* __restrict__ Wv)
{
    int i = (blockIdx.x * 256 + threadIdx.x) * 2;
    __half h0, l0, h1, l1;
    if (i < 16384) {
        split2(Wq[i], h0, l0); split2(Wq[i + 1], h1, l1);
        *(uint32_t*)&g_wqh[i] = pack2(h0, h1);
        *(uint32_t*)&g_wql[i] = pack2(l0, l1);
    } else if (i < 32768) {
        int j = i - 16384;
        split2(Wk[j], h0, l0); split2(Wk[j + 1], h1, l1);
        *(uint32_t*)&g_wkh[j] = pack2(h0, h1);
        *(uint32_t*)&g_wkl[j] = pack2(l0, l1);
    } else {
        int j = i - 32768;
        *(uint32_t*)&g_wv16[j] = pack2(__float2half_rn(Wv[j]), __float2half_rn(Wv[j + 1]));
    }
}

// ---------------------------------------------------------------------------
// megaproj: blockIdx.x selects path. 0=q, 1=k (3-term split, 128p x 64d),
// 2/3 = v o-half (1-term, 128p x 128o). 256 threads, 73728 B smem, 3 blk/SM.
// x is fastest dispatch dim -> k/v blocks of same tile share flow via L2.
// ---------------------------------------------------------------------------
#define MP_SMEM 73728
__global__ __launch_bounds__(256, 3) void megaproj(
    const float* __restrict__ de_out, const float* __restrict__ flow,
    const float* __restrict__ bq, const float* __restrict__ bk,
    const float* __restrict__ bv)
{
    extern __shared__ __half smh[];
    const int tid = threadIdx.x, w = tid >> 5, lane = tid & 31;
    const int c = lane & 3, g = lane >> 2;
    const int wm = w & 3, wn = w >> 2;
    const int type = blockIdx.x;
    const int p0 = blockIdx.y * 128, b = blockIdx.z;

    if (type < 2) {
        // ---------------- q/k path (3-term split) ----------------
        const int isK = type;
        __half* xh = smh;
        __half* xl = smh + 9216;

        const float*  X    = isK ? flow : de_out;
        const float*  bias = isK ? bk : bq;
        const __half* wsh  = isK ? g_wkh : g_wqh;
        const __half* wsl  = isK ? g_wkl : g_wql;
        __half*       Yh   = isK ? g_kh : g_qh;
        __half*       Yl   = isK ? g_kl : g_ql;
        const float* Xb = X + (size_t)b * Cn * HWn;

        float acc[2][4][4] = {};

        {
            __half* wb = smh + 18432;
            for (int i = tid; i < 512; i += 256) {
                int d = i >> 3, s = (i & 7) * 8;
                CP16(sptr(wb + d * PS + s), wsh + d * 256 + s);
                CP16(sptr(wb + 4608 + d * PS + s), wsl + d * 256 + s);
            }
            CPCOMMIT();
        }

        for (int kc = 0; kc < 4; kc++) {
            if (kc < 3) {
                __half* wb = smh + 18432 + ((kc + 1) & 1) * 9216;
                for (int i = tid; i < 512; i += 256) {
                    int d = i >> 3, s = (i & 7) * 8;
                    CP16(sptr(wb + d * PS + s), wsh + d * 256 + (kc + 1) * 64 + s);
                    CP16(sptr(wb + 4608 + d * PS + s), wsl + d * 256 + (kc + 1) * 64 + s);
                }
                CPCOMMIT();
            }
            for (int i = tid; i < 2048; i += 256) {
                int p = i & 127, cg = i >> 7;
                const float* src = &Xb[(size_t)(kc * 64 + cg * 4) * HWn + p0 + p];
                __half h0, l0, h1, l1;
                uint2 hv, lv;
                split2(src[0], h0, l0);
                split2(src[(size_t)HWn], h1, l1);
                hv.x = pack2(h0, h1); lv.x = pack2(l0, l1);
                split2(src[2 * (size_t)HWn], h0, l0);
                split2(src[3 * (size_t)HWn], h1, l1);
                hv.y = pack2(h0, h1); lv.y = pack2(l0, l1);
                *(uint2*)&xh[p * PS + cg * 4] = hv;
                *(uint2*)&xl[p * PS + cg * 4] = lv;
            }
            if (kc < 3) CPWAIT(1); else CPWAIT(0);
            __syncthreads();

            const __half* wh = smh + 18432 + (kc & 1) * 9216;
            const __half* wl = wh + 4608;
#pragma unroll
            for (int kt = 0; kt < 4; kt++) {
                uint32_t ah0[4], al0[4], ah1[4], al1[4];
                ldmA(ah0, xh, wm * 32, kt * 16, lane, PS);
                ldmA(al0, xl, wm * 32, kt * 16, lane, PS);
                ldmA(ah1, xh, wm * 32 + 16, kt * 16, lane, PS);
                ldmA(al1, xl, wm * 32 + 16, kt * 16, lane, PS);
#pragma unroll
                for (int nt = 0; nt < 4; nt += 2) {
                    uint32_t bh[4], bl[4];
                    ldmB2(bh, wh, wn * 32 + nt * 8, kt * 16, lane, PS);
                    ldmB2(bl, wl, wn * 32 + nt * 8, kt * 16, lane, PS);
                    mma16816(acc[0][nt], ah0, bh);
                    mma16816(acc[0][nt], ah0, bl);
                    mma16816(acc[0][nt], al0, bh);
                    mma16816(acc[1][nt], ah1, bh);
                    mma16816(acc[1][nt], ah1, bl);
                    mma16816(acc[1][nt], al1, bh);
                    mma16816(acc[0][nt + 1], ah0, bh + 2);
                    mma16816(acc[0][nt + 1], ah0, bl + 2);
                    mma16816(acc[0][nt + 1], al0, bh + 2);
                    mma16816(acc[1][nt + 1], ah1, bh + 2);
                    mma16816(acc[1][nt + 1], ah1, bl + 2);
                    mma16816(acc[1][nt + 1], al1, bh + 2);
                }
            }
            __syncthreads();
        }
#pragma unroll
        for (int mt = 0; mt < 2; mt++) {
#pragma unroll
            for (int nt = 0; nt < 4; nt++) {
                int dcol = wn * 32 + nt * 8 + 2 * c;
                float b0 = bias[dcol], b1 = bias[dcol + 1];
                size_t r0 = ((size_t)b * HWn + p0 + wm * 32 + mt * 16 + g) * 64 + dcol;
                size_t r1 = r0 + (size_t)8 * 64;
                __half h0, l0, h1, l1;
                split2(acc[mt][nt][0] + b0, h0, l0);
                split2(acc[mt][nt][1] + b1, h1, l1);
                *(uint32_t*)&Yh[r0] = pack2(h0, h1);
                *(uint32_t*)&Yl[r0] = pack2(l0, l1);
                split2(acc[mt][nt][2] + b0, h0, l0);
                split2(acc[mt][nt][3] + b1, h1, l1);
                *(uint32_t*)&Yh[r1] = pack2(h0, h1);
                *(uint32_t*)&Yl[r1] = pack2(l0, l1);
            }
        }
    } else {
        // ---------------- v path (1-term, o-half per block) ----------------
        const int ohalf = type - 2;
        __half* xs = smh;                          // [128 p][72] hi only
        const float* Xb = flow + (size_t)b * Cn * HWn;
        const __half* wsrc = g_wv16 + (size_t)(ohalf * 128) * 256;

        // issue W chunk 0 ([128 o][64 c])
        {
            __half* wb = smh + 18432;
            for (int i = tid; i < 1024; i += 256) {
                int o = i >> 3, s = (i & 7) * 8;
                CP16(sptr(wb + o * PS + s), wsrc + o * 256 + s);
            }
            CPCOMMIT();
        }

        float acc[2][8][4] = {};

        for (int kc = 0; kc < 4; kc++) {
            if (kc < 3) {
                __half* wb = smh + 18432 + ((kc + 1) & 1) * 9216;
                for (int i = tid; i < 1024; i += 256) {
                    int o = i >> 3, s = (i & 7) * 8;
                    CP16(sptr(wb + o * PS + s), wsrc + o * 256 + (kc + 1) * 64 + s);
                }
                CPCOMMIT();
            }
            // stage X hi chunk [128 p][64 c]
            for (int i = tid; i < 2048; i += 256) {
                int p = i & 127, cg = i >> 7;
                const float* src = &Xb[(size_t)(kc * 64 + cg * 4) * HWn + p0 + p];
                uint2 hv;
                hv.x = pack2(__float2half_rn(src[0]), __float2half_rn(src[(size_t)HWn]));
                hv.y = pack2(__float2half_rn(src[2 * (size_t)HWn]),
                             __float2half_rn(src[3 * (size_t)HWn]));
                *(uint2*)&xs[p * PS + cg * 4] = hv;
            }
            if (kc < 3) CPWAIT(1); else CPWAIT(0);
            __syncthreads();

            const __half* wb = smh + 18432 + (kc & 1) * 9216;
#pragma unroll
            for (int kt = 0; kt < 4; kt++) {
                uint32_t a0[4], a1[4];
                ldmA(a0, xs, wm * 32, kt * 16, lane, PS);
                ldmA(a1, xs, wm * 32 + 16, kt * 16, lane, PS);
#pragma unroll
                for (int ntp = 0; ntp < 4; ntp++) {
                    uint32_t bb[4];
                    ldmB2(bb, wb, wn * 64 + ntp * 16, kt * 16, lane, PS);
                    mma16816(acc[0][2 * ntp], a0, bb);
                    mma16816(acc[1][2 * ntp], a1, bb);
                    mma16816(acc[0][2 * ntp + 1], a0, bb + 2);
                    mma16816(acc[1][2 * ntp + 1], a1, bb + 2);
                }
            }
            __syncthreads();
        }
#pragma unroll
        for (int mt = 0; mt < 2; mt++) {
#pragma unroll
            for (int nt = 0; nt < 8; nt++) {
                int o = ohalf * 128 + wn * 64 + nt * 8 + 2 * c;
                int p = p0 + wm * 32 + mt * 16 + g;
                float b0 = bv[o], b1 = bv[o + 1];
                g_v[(size_t)(b * 256 + o) * HWn + p]         = __float2half_rn(acc[mt][nt][0] + b0);
                g_v[(size_t)(b * 256 + o + 1) * HWn + p]     = __float2half_rn(acc[mt][nt][1] + b1);
                g_v[(size_t)(b * 256 + o) * HWn + p + 8]     = __float2half_rn(acc[mt][nt][2] + b0);
                g_v[(size_t)(b * 256 + o + 1) * HWn + p + 8] = __float2half_rn(acc[mt][nt][3] + b1);
            }
        }
    }
}

// ---------------------------------------------------------------------------
// Fused attention (R10 v1, known-good): E (3-term) -> warp softmax -> AV
// (1-term). grid (2, 128, B), 256 threads.
// ---------------------------------------------------------------------------
#define A_SMEM (110592 + 67584)
__global__ __launch_bounds__(256, 1) void attn(float* __restrict__ out)
{
    extern __shared__ __half smh[];
    __half* qh = smh;
    __half* ql = qh + 128 * PS;
    __half* kh = ql + 128 * PS;
    __half* kl = kh + 256 * PS;
    __half* vs0 = smh + 55296;
    __half* vs1 = smh;

    const int tid = threadIdx.x, w = tid >> 5, lane = tid & 31;
    const int c = lane & 3, g = lane >> 2;
    const int qt = blockIdx.x, h = blockIdx.y, b = blockIdx.z;
    const int w0 = qt * 128;
    const __half* vg = g_v + (size_t)b * 256 * HWn + h * Wn;

    {
        const __half* qsh = g_qh + ((size_t)b * HWn + h * Wn + w0) * 64;
        const __half* qsl = g_ql + ((size_t)b * HWn + h * Wn + w0) * 64;
        const __half* ksh = g_kh + ((size_t)b * HWn + h * Wn) * 64;
        const __half* ksl = g_kl + ((size_t)b * HWn + h * Wn) * 64;
        for (int i = tid; i < 1024; i += 256) {
            int r = i >> 3, s = (i & 7) * 8;
            CP16(sptr(qh + r * PS + s), qsh + r * 64 + s);
            CP16(sptr(ql + r * PS + s), qsl + r * 64 + s);
        }
        for (int i = tid; i < 2048; i += 256) {
            int r = i >> 3, s = (i & 7) * 8;
            CP16(sptr(kh + r * PS + s), ksh + r * 64 + s);
            CP16(sptr(kl + r * PS + s), ksl + r * 64 + s);
        }
        CPCOMMIT();
    }
    for (int i = tid; i < 4096; i += 256) {
        int o = i >> 5, s = (i & 31) * 8;
        CP16(sptr(vs0 + o * PSV + s), vg + (size_t)o * HWn + s);
    }
    CPCOMMIT();

    CPWAIT(1);
    __syncthreads();

    float e[32][4] = {};
#pragma unroll
    for (int kt = 0; kt < 4; kt++) {
        uint32_t ah[4], al[4];
        ldmA(ah, qh, w * 16, kt * 16, lane, PS);
        ldmA(al, ql, w * 16, kt * 16, lane, PS);
#pragma unroll
        for (int nt = 0; nt < 32; nt += 2) {
            uint32_t bh[4], bl[4];
            ldmB2(bh, kh, nt * 8, kt * 16, lane, PS);
            ldmB2(bl, kl, nt * 8, kt * 16, lane, PS);
            mma16816(e[nt], ah, bh);
            mma16816(e[nt], ah, bl);
            mma16816(e[nt], al, bh);
            mma16816(e[nt + 1], ah, bh + 2);
            mma16816(e[nt + 1], ah, bl + 2);
            mma16816(e[nt + 1], al, bh + 2);
        }
    }
    __syncthreads();

    for (int i = tid; i < 4096; i += 256) {
        int o = i >> 5, s = (i & 31) * 8;
        CP16(sptr(vs1 + o * PSV + s), vg + (size_t)(o + 128) * HWn + s);
    }
    CPCOMMIT();

    float m0 = -1e30f, m1 = -1e30f;
#pragma unroll
    for (int nt = 0; nt < 32; nt++) {
        m0 = fmaxf(m0, fmaxf(e[nt][0], e[nt][1]));
        m1 = fmaxf(m1, fmaxf(e[nt][2], e[nt][3]));
    }
    m0 = fmaxf(m0, __shfl_xor_sync(0xffffffffu, m0, 1));
    m0 = fmaxf(m0, __shfl_xor_sync(0xffffffffu, m0, 2));
    m1 = fmaxf(m1, __shfl_xor_sync(0xffffffffu, m1, 1));
    m1 = fmaxf(m1, __shfl_xor_sync(0xffffffffu, m1, 2));

    float s0 = 0.f, s1 = 0.f;
    uint32_t ah_[64];
#pragma unroll
    for (int nt = 0; nt < 32; nt++) {
        float p00 = __expf(e[nt][0] - m0), p01 = __expf(e[nt][1] - m0);
        float p10 = __expf(e[nt][2] - m1), p11 = __expf(e[nt][3] - m1);
        s0 += p00 + p01;
        s1 += p10 + p11;
        ah_[2 * nt]     = pack2(__float2half_rn(p00), __float2half_rn(p01));
        ah_[2 * nt + 1] = pack2(__float2half_rn(p10), __float2half_rn(p11));
    }
    s0 += __shfl_xor_sync(0xffffffffu, s0, 1);
    s0 += __shfl_xor_sync(0xffffffffu, s0, 2);
    s1 += __shfl_xor_sync(0xffffffffu, s1, 1);
    s1 += __shfl_xor_sync(0xffffffffu, s1, 2);
    const float rinv0 = 1.0f / s0, rinv1 = 1.0f / s1;

    CPWAIT(1);
    __syncthreads();
    {
        float oacc[16][4] = {};
#pragma unroll
        for (int kt = 0; kt < 16; kt++) {
            const uint32_t* Ah = &ah_[4 * kt];
#pragma unroll
            for (int nt = 0; nt < 16; nt += 2) {
                uint32_t bb[4];
                ldmB2(bb, vs0, nt * 8, kt * 16, lane, PSV);
                mma16816(oacc[nt], Ah, bb);
                mma16816(oacc[nt + 1], Ah, bb + 2);
            }
        }
#pragma unroll
        for (int nt = 0; nt < 16; nt++) {
            int o = nt * 8 + 2 * c;
            size_t i0 = (size_t)(b * 256 + o) * HWn + h * Wn + w0 + w * 16 + g;
            out[i0]           = oacc[nt][0] * rinv0;
            out[i0 + HWn]     = oacc[nt][1] * rinv0;
            out[i0 + 8]       = oacc[nt][2] * rinv1;
            out[i0 + HWn + 8] = oacc[nt][3] * rinv1;
        }
    }

    CPWAIT(0);
    __syncthreads();
    {
        float oacc[16][4] = {};
#pragma unroll
        for (int kt = 0; kt < 16; kt++) {
            const uint32_t* Ah = &ah_[4 * kt];
#pragma unroll
            for (int nt = 0; nt < 16; nt += 2) {
                uint32_t bb[4];
                ldmB2(bb, vs1, nt * 8, kt * 16, lane, PSV);
                mma16816(oacc[nt], Ah, bb);
                mma16816(oacc[nt + 1], Ah, bb + 2);
            }
        }
#pragma unroll
        for (int nt = 0; nt < 16; nt++) {
            int o = 128 + nt * 8 + 2 * c;
            size_t i0 = (size_t)(b * 256 + o) * HWn + h * Wn + w0 + w * 16 + g;
            out[i0]           = oacc[nt][0] * rinv0;
            out[i0 + HWn]     = oacc[nt][1] * rinv0;
            out[i0 + 8]       = oacc[nt][2] * rinv1;
            out[i0 + HWn + 8] = oacc[nt][3] * rinv1;
        }
    }
}

// ---------------------------------------------------------------------------
extern "C" void kernel_launch(void* const* d_in, const int* in_sizes, int n_in,
                              void* d_out, int out_size)
{
    const float* flow   = (const float*)d_in[0];
    const float* de_out = (const float*)d_in[1];
    const float* Wq     = (const float*)d_in[2];
    const float* bq     = (const float*)d_in[3];
    const float* Wk     = (const float*)d_in[4];
    const float* bk     = (const float*)d_in[5];
    const float* Wv     = (const float*)d_in[6];
    const float* bv     = (const float*)d_in[7];
    float* out = (float*)d_out;

    cudaFuncSetAttribute(megaproj, cudaFuncAttributeMaxDynamicSharedMemorySize, MP_SMEM);
    cudaFuncSetAttribute(attn,     cudaFuncAttributeMaxDynamicSharedMemorySize, A_SMEM);

    prep<<<192, 256>>>(Wq, Wk, Wv);
    megaproj<<<dim3(4, HWn / 128, Bn), 256, MP_SMEM>>>(de_out, flow, bq, bk, bv);
    attn<<<dim3(Wn / 128, Hn, Bn), 256, A_SMEM>>>(out);
}

// round 14
// speedup vs baseline: 1.1268x; 1.0136x over previous
#include <cuda_runtime.h>
#include <cuda_fp16.h>
#include <cstdint>

#define Bn 4
#define Cn 256
#define Hn 128
#define Wn 256
#define HWn 32768
#define PS 72    // smem stride (halves), 64-wide tiles
#define PSV 264  // smem stride (halves), 256-wide rows

// q,k pre-split hi/lo fp16 [b][p][64]; v plain fp16 [b][o][p]
__device__ __half g_qh[(size_t)Bn * HWn * 64];
__device__ __half g_ql[(size_t)Bn * HWn * 64];
__device__ __half g_kh[(size_t)Bn * HWn * 64];
__device__ __half g_kl[(size_t)Bn * HWn * 64];
__device__ __half g_v [(size_t)Bn * 256 * HWn];
// pre-converted weights
__device__ __half g_wqh[64 * 256], g_wql[64 * 256];
__device__ __half g_wkh[64 * 256], g_wkl[64 * 256];
__device__ __half g_wv16[256 * 256];

// ---------------- helpers ----------------
static __device__ __forceinline__ void split2(float x, __half& h, __half& l) {
    h = __float2half_rn(x);
    l = __float2half_rn(x - __half2float(h));
}
static __device__ __forceinline__ uint32_t pack2(__half a, __half b) {
    __half2 t = __halves2half2(a, b);
    return *(uint32_t*)&t;
}
static __device__ __forceinline__ uint32_t sptr(const void* p) {
    return (uint32_t)__cvta_generic_to_shared(p);
}
static __device__ __forceinline__ void mma16816(float* d, const uint32_t* a, const uint32_t* b) {
    asm volatile("mma.sync.aligned.m16n8k16.row.col.f32.f16.f16.f32 "
        "{%0,%1,%2,%3}, {%4,%5,%6,%7}, {%8,%9}, {%0,%1,%2,%3};"
        : "+f"(d[0]), "+f"(d[1]), "+f"(d[2]), "+f"(d[3])
        : "r"(a[0]), "r"(a[1]), "r"(a[2]), "r"(a[3]), "r"(b[0]), "r"(b[1]));
}
static __device__ __forceinline__ void ldmA(uint32_t* a, const __half* t, int m0, int k0,
                                            int lane, int stride) {
    const __half* p = t + (m0 + (lane & 15)) * stride + k0 + ((lane >> 4) << 3);
    asm volatile("ldmatrix.sync.aligned.m8n8.x4.shared.b16 {%0,%1,%2,%3}, [%4];"
        : "=r"(a[0]), "=r"(a[1]), "=r"(a[2]), "=r"(a[3]) : "r"(sptr(p)));
}
static __device__ __forceinline__ void ldmB2(uint32_t* b, const __half* t, int n0, int k0,
                                             int lane, int stride) {
    int grp = lane >> 3;
    const __half* p = t + (n0 + ((grp & 2) << 2) + (lane & 7)) * stride + k0 + ((grp & 1) << 3);
    asm volatile("ldmatrix.sync.aligned.m8n8.x4.shared.b16 {%0,%1,%2,%3}, [%4];"
        : "=r"(b[0]), "=r"(b[1]), "=r"(b[2]), "=r"(b[3]) : "r"(sptr(p)));
}
#define CP16(d, s)  asm volatile("cp.async.cg.shared.global [%0], [%1], 16;" :: "r"(d), "l"(s))
#define CPCOMMIT()  asm volatile("cp.async.commit_group;")
#define CPWAIT(n)   asm volatile("cp.async.wait_group %0;" :: "n"(n) : "memory")

// ---------------------------------------------------------------------------
// prep: Wq/Wk -> hi/lo fp16, Wv -> fp16
// ---------------------------------------------------------------------------
__global__ void prep(const float* __restrict__ Wq, const float* __restrict__ Wk,
                     const float* __restrict__ Wv)
{
    int i = (blockIdx.x * 256 + threadIdx.x) * 2;
    __half h0, l0, h1, l1;
    if (i < 16384) {
        split2(Wq[i], h0, l0); split2(Wq[i + 1], h1, l1);
        *(uint32_t*)&g_wqh[i] = pack2(h0, h1);
        *(uint32_t*)&g_wql[i] = pack2(l0, l1);
    } else if (i < 32768) {
        int j = i - 16384;
        split2(Wk[j], h0, l0); split2(Wk[j + 1], h1, l1);
        *(uint32_t*)&g_wkh[j] = pack2(h0, h1);
        *(uint32_t*)&g_wkl[j] = pack2(l0, l1);
    } else {
        int j = i - 32768;
        *(uint32_t*)&g_wv16[j] = pack2(__float2half_rn(Wv[j]), __float2half_rn(Wv[j + 1]));
    }
}

// ---------------------------------------------------------------------------
// q/k projection (3-term split): D[128 p, 64 d] = X^T * W^T + bias
// grid (HWn/128, 2, B), 256 threads. (R10 proven version)
// ---------------------------------------------------------------------------
#define QK_SMEM 73728
__global__ __launch_bounds__(256) void qk_proj(
    const float* __restrict__ de_out, const float* __restrict__ flow,
    const float* __restrict__ bq, const float* __restrict__ bk)
{
    extern __shared__ __half smh[];
    __half* xh = smh;
    __half* xl = smh + 9216;

    const int tid = threadIdx.x, w = tid >> 5, lane = tid & 31;
    const int c = lane & 3, g = lane >> 2;
    const int wm = w & 3, wn = w >> 2;
    const int p0 = blockIdx.x * 128, isK = blockIdx.y, b = blockIdx.z;

    const float*  X    = isK ? flow : de_out;
    const float*  bias = isK ? bk : bq;
    const __half* wsh  = isK ? g_wkh : g_wqh;
    const __half* wsl  = isK ? g_wkl : g_wql;
    __half*       Yh   = isK ? g_kh : g_qh;
    __half*       Yl   = isK ? g_kl : g_ql;
    const float* Xb = X + (size_t)b * Cn * HWn;

    float acc[2][4][4] = {};

    {
        __half* wb = smh + 18432;
        for (int i = tid; i < 512; i += 256) {
            int d = i >> 3, s = (i & 7) * 8;
            CP16(sptr(wb + d * PS + s), wsh + d * 256 + s);
            CP16(sptr(wb + 4608 + d * PS + s), wsl + d * 256 + s);
        }
        CPCOMMIT();
    }

    for (int kc = 0; kc < 4; kc++) {
        if (kc < 3) {
            __half* wb = smh + 18432 + ((kc + 1) & 1) * 9216;
            for (int i = tid; i < 512; i += 256) {
                int d = i >> 3, s = (i & 7) * 8;
                CP16(sptr(wb + d * PS + s), wsh + d * 256 + (kc + 1) * 64 + s);
                CP16(sptr(wb + 4608 + d * PS + s), wsl + d * 256 + (kc + 1) * 64 + s);
            }
            CPCOMMIT();
        }
        for (int i = tid; i < 2048; i += 256) {
            int p = i & 127, cg = i >> 7;
            const float* src = &Xb[(size_t)(kc * 64 + cg * 4) * HWn + p0 + p];
            __half h0, l0, h1, l1;
            uint2 hv, lv;
            split2(src[0], h0, l0);
            split2(src[(size_t)HWn], h1, l1);
            hv.x = pack2(h0, h1); lv.x = pack2(l0, l1);
            split2(src[2 * (size_t)HWn], h0, l0);
            split2(src[3 * (size_t)HWn], h1, l1);
            hv.y = pack2(h0, h1); lv.y = pack2(l0, l1);
            *(uint2*)&xh[p * PS + cg * 4] = hv;
            *(uint2*)&xl[p * PS + cg * 4] = lv;
        }
        if (kc < 3) CPWAIT(1); else CPWAIT(0);
        __syncthreads();

        const __half* wh = smh + 18432 + (kc & 1) * 9216;
        const __half* wl = wh + 4608;
#pragma unroll
        for (int kt = 0; kt < 4; kt++) {
            uint32_t ah0[4], al0[4], ah1[4], al1[4];
            ldmA(ah0, xh, wm * 32, kt * 16, lane, PS);
            ldmA(al0, xl, wm * 32, kt * 16, lane, PS);
            ldmA(ah1, xh, wm * 32 + 16, kt * 16, lane, PS);
            ldmA(al1, xl, wm * 32 + 16, kt * 16, lane, PS);
#pragma unroll
            for (int nt = 0; nt < 4; nt += 2) {
                uint32_t bh[4], bl[4];
                ldmB2(bh, wh, wn * 32 + nt * 8, kt * 16, lane, PS);
                ldmB2(bl, wl, wn * 32 + nt * 8, kt * 16, lane, PS);
                mma16816(acc[0][nt], ah0, bh);
                mma16816(acc[0][nt], ah0, bl);
                mma16816(acc[0][nt], al0, bh);
                mma16816(acc[1][nt], ah1, bh);
                mma16816(acc[1][nt], ah1, bl);
                mma16816(acc[1][nt], al1, bh);
                mma16816(acc[0][nt + 1], ah0, bh + 2);
                mma16816(acc[0][nt + 1], ah0, bl + 2);
                mma16816(acc[0][nt + 1], al0, bh + 2);
                mma16816(acc[1][nt + 1], ah1, bh + 2);
                mma16816(acc[1][nt + 1], ah1, bl + 2);
                mma16816(acc[1][nt + 1], al1, bh + 2);
            }
        }
        __syncthreads();
    }
#pragma unroll
    for (int mt = 0; mt < 2; mt++) {
#pragma unroll
        for (int nt = 0; nt < 4; nt++) {
            int dcol = wn * 32 + nt * 8 + 2 * c;
            float b0 = bias[dcol], b1 = bias[dcol + 1];
            size_t r0 = ((size_t)b * HWn + p0 + wm * 32 + mt * 16 + g) * 64 + dcol;
            size_t r1 = r0 + (size_t)8 * 64;
            __half h0, l0, h1, l1;
            split2(acc[mt][nt][0] + b0, h0, l0);
            split2(acc[mt][nt][1] + b1, h1, l1);
            *(uint32_t*)&Yh[r0] = pack2(h0, h1);
            *(uint32_t*)&Yl[r0] = pack2(l0, l1);
            split2(acc[mt][nt][2] + b0, h0, l0);
            split2(acc[mt][nt][3] + b1, h1, l1);
            *(uint32_t*)&Yh[r1] = pack2(h0, h1);
            *(uint32_t*)&Yl[r1] = pack2(l0, l1);
        }
    }
}

// ---------------------------------------------------------------------------
// v projection (1-term): D[128 p, 256 o] -> g_v fp16 [b][o][p]
// grid (HWn/128, 1, B), 256 threads, 2 blocks/SM. (R10 proven version)
// ---------------------------------------------------------------------------
#define V_SMEM (67584 + 2 * 18432)
static __device__ __forceinline__ void issue_wv_tile(__half* smh, int tid, int t) {
    __half* wb = smh + 33792 + (t & 1) * 9216;
    int oh = t >> 2, kc = t & 3;
    for (int i = tid; i < 1024; i += 256) {
        int o = i >> 3, s = (i & 7) * 8;
        CP16(sptr(wb + o * PS + s), g_wv16 + (size_t)(oh * 128 + o) * 256 + kc * 64 + s);
    }
    CPCOMMIT();
}
__global__ __launch_bounds__(256, 2) void v_proj(
    const float* __restrict__ flow, const float* __restrict__ bv)
{
    extern __shared__ __half smh[];
    __half* xs = smh;   // [128][264]

    const int tid = threadIdx.x, w = tid >> 5, lane = tid & 31;
    const int c = lane & 3, g = lane >> 2;
    const int wm = w & 3, wn = w >> 2;
    const int p0 = blockIdx.x * 128, b = blockIdx.z;
    const float* Xb = flow + (size_t)b * Cn * HWn;

    issue_wv_tile(smh, tid, 0);
    issue_wv_tile(smh, tid, 1);

    for (int i = tid; i < 8192; i += 256) {
        int p = i & 127, cg = i >> 7;
        const float* src = &Xb[(size_t)(cg * 4) * HWn + p0 + p];
        uint2 hv;
        hv.x = pack2(__float2half_rn(src[0]), __float2half_rn(src[(size_t)HWn]));
        hv.y = pack2(__float2half_rn(src[2 * (size_t)HWn]), __float2half_rn(src[3 * (size_t)HWn]));
        *(uint2*)&xs[p * PSV + cg * 4] = hv;
    }
    __syncthreads();

    for (int oh = 0; oh < 2; oh++) {
        float acc[2][8][4] = {};
        for (int kc = 0; kc < 4; kc++) {
            int t = oh * 4 + kc;
            if (t < 7) CPWAIT(1); else CPWAIT(0);
            __syncthreads();
            const __half* wb = smh + 33792 + (t & 1) * 9216;
#pragma unroll
            for (int ktc = 0; ktc < 4; ktc++) {
                uint32_t a0[4], a1[4];
                ldmA(a0, xs, wm * 32, kc * 64 + ktc * 16, lane, PSV);
                ldmA(a1, xs, wm * 32 + 16, kc * 64 + ktc * 16, lane, PSV);
#pragma unroll
                for (int ntp = 0; ntp < 4; ntp++) {
                    uint32_t bb[4];
                    ldmB2(bb, wb, wn * 64 + ntp * 16, ktc * 16, lane, PS);
                    mma16816(acc[0][2 * ntp], a0, bb);
                    mma16816(acc[1][2 * ntp], a1, bb);
                    mma16816(acc[0][2 * ntp + 1], a0, bb + 2);
                    mma16816(acc[1][2 * ntp + 1], a1, bb + 2);
                }
            }
            __syncthreads();
            if (t + 2 <= 7) issue_wv_tile(smh, tid, t + 2);
        }
#pragma unroll
        for (int mt = 0; mt < 2; mt++) {
#pragma unroll
            for (int nt = 0; nt < 8; nt++) {
                int o = oh * 128 + wn * 64 + nt * 8 + 2 * c;
                int p = p0 + wm * 32 + mt * 16 + g;
                float b0 = bv[o], b1 = bv[o + 1];
                g_v[(size_t)(b * 256 + o) * HWn + p]         = __float2half_rn(acc[mt][nt][0] + b0);
                g_v[(size_t)(b * 256 + o + 1) * HWn + p]     = __float2half_rn(acc[mt][nt][1] + b1);
                g_v[(size_t)(b * 256 + o) * HWn + p + 8]     = __float2half_rn(acc[mt][nt][2] + b0);
                g_v[(size_t)(b * 256 + o + 1) * HWn + p + 8] = __float2half_rn(acc[mt][nt][3] + b1);
            }
        }
    }
}

// ---------------------------------------------------------------------------
// Fused attention v3: E + softmax as R10 (warp owns 16 q x 256 k, att in regs
// until exp), then att stored to smem fp16 and AV re-tiled 2D:
// warp = 64 q x 32 o per chunk -> 6 ldmatrix per 16 MMA (was 8).
// smem (halves): [q/k: qh 0, ql 9216, kh 18432, kl 36864 .. 55296]
// aliased after E by: att 0..33792 | vs1 33792..67584 ; vs0 67584..101376.
// Total 202752 B. rsinv[128] static.
// ---------------------------------------------------------------------------
#define A_SMEM 202752
__global__ __launch_bounds__(256, 1) void attn(float* __restrict__ out)
{
    extern __shared__ __half smh[];
    __half* qh  = smh;
    __half* ql  = smh + 9216;
    __half* kh  = smh + 18432;
    __half* kl  = smh + 36864;
    __half* att = smh;             // alias after E
    __half* vs1 = smh + 33792;     // alias after E
    __half* vs0 = smh + 67584;
    __shared__ float rsinv[128];

    const int tid = threadIdx.x, w = tid >> 5, lane = tid & 31;
    const int c = lane & 3, g = lane >> 2;
    const int qt = blockIdx.x, h = blockIdx.y, b = blockIdx.z;
    const int w0 = qt * 128;
    const __half* vg = g_v + (size_t)b * 256 * HWn + h * Wn;

    // group 0: q/k hi+lo ; group 1: vs0 (overlaps E)
    {
        const __half* qsh = g_qh + ((size_t)b * HWn + h * Wn + w0) * 64;
        const __half* qsl = g_ql + ((size_t)b * HWn + h * Wn + w0) * 64;
        const __half* ksh = g_kh + ((size_t)b * HWn + h * Wn) * 64;
        const __half* ksl = g_kl + ((size_t)b * HWn + h * Wn) * 64;
        for (int i = tid; i < 1024; i += 256) {
            int r = i >> 3, s = (i & 7) * 8;
            CP16(sptr(qh + r * PS + s), qsh + r * 64 + s);
            CP16(sptr(ql + r * PS + s), qsl + r * 64 + s);
        }
        for (int i = tid; i < 2048; i += 256) {
            int r = i >> 3, s = (i & 7) * 8;
            CP16(sptr(kh + r * PS + s), ksh + r * 64 + s);
            CP16(sptr(kl + r * PS + s), ksl + r * 64 + s);
        }
        CPCOMMIT();
    }
    for (int i = tid; i < 4096; i += 256) {
        int o = i >> 5, s = (i & 31) * 8;
        CP16(sptr(vs0 + o * PSV + s), vg + (size_t)o * HWn + s);
    }
    CPCOMMIT();

    CPWAIT(1);
    __syncthreads();

    // E = q k^T : warp rows w*16, all 256 keys (3-term split)
    float e[32][4] = {};
#pragma unroll
    for (int kt = 0; kt < 4; kt++) {
        uint32_t ah[4], al[4];
        ldmA(ah, qh, w * 16, kt * 16, lane, PS);
        ldmA(al, ql, w * 16, kt * 16, lane, PS);
#pragma unroll
        for (int nt = 0; nt < 32; nt += 2) {
            uint32_t bh[4], bl[4];
            ldmB2(bh, kh, nt * 8, kt * 16, lane, PS);
            ldmB2(bl, kl, nt * 8, kt * 16, lane, PS);
            mma16816(e[nt], ah, bh);
            mma16816(e[nt], ah, bl);
            mma16816(e[nt], al, bh);
            mma16816(e[nt + 1], ah, bh + 2);
            mma16816(e[nt + 1], ah, bl + 2);
            mma16816(e[nt + 1], al, bh + 2);
        }
    }
    __syncthreads();   // q/k smem dead from here

    // vs1 -> aliased region (overlaps softmax + AV chunk0)
    for (int i = tid; i < 4096; i += 256) {
        int o = i >> 5, s = (i & 31) * 8;
        CP16(sptr(vs1 + o * PSV + s), vg + (size_t)(o + 128) * HWn + s);
    }
    CPCOMMIT();

    // warp-local softmax; att written to smem fp16 (conflict-free pattern)
    const int row0 = w * 16 + g, row1 = row0 + 8;
    float m0 = -1e30f, m1 = -1e30f;
#pragma unroll
    for (int nt = 0; nt < 32; nt++) {
        m0 = fmaxf(m0, fmaxf(e[nt][0], e[nt][1]));
        m1 = fmaxf(m1, fmaxf(e[nt][2], e[nt][3]));
    }
    m0 = fmaxf(m0, __shfl_xor_sync(0xffffffffu, m0, 1));
    m0 = fmaxf(m0, __shfl_xor_sync(0xffffffffu, m0, 2));
    m1 = fmaxf(m1, __shfl_xor_sync(0xffffffffu, m1, 1));
    m1 = fmaxf(m1, __shfl_xor_sync(0xffffffffu, m1, 2));

    float s0 = 0.f, s1 = 0.f;
    uint32_t* att32 = (uint32_t*)att;
#pragma unroll
    for (int nt = 0; nt < 32; nt++) {
        float p00 = __expf(e[nt][0] - m0), p01 = __expf(e[nt][1] - m0);
        float p10 = __expf(e[nt][2] - m1), p11 = __expf(e[nt][3] - m1);
        s0 += p00 + p01;
        s1 += p10 + p11;
        att32[row0 * 132 + 4 * nt + c] = pack2(__float2half_rn(p00), __float2half_rn(p01));
        att32[row1 * 132 + 4 * nt + c] = pack2(__float2half_rn(p10), __float2half_rn(p11));
    }
    s0 += __shfl_xor_sync(0xffffffffu, s0, 1);
    s0 += __shfl_xor_sync(0xffffffffu, s0, 2);
    s1 += __shfl_xor_sync(0xffffffffu, s1, 1);
    s1 += __shfl_xor_sync(0xffffffffu, s1, 2);
    if (c == 0) {
        rsinv[row0] = 1.0f / s0;
        rsinv[row1] = 1.0f / s1;
    }

    CPWAIT(1);        // vs0 arrived (vs1 may still be in flight)
    __syncthreads();  // att + rsinv + vs0 visible

    // AV re-tiled: warp = q rows qg*64..+64 (4 tiles), o cols og*32..+32 (4 tiles)
    const int qg = w >> 2, og = w & 3;
    for (int ch = 0; ch < 2; ch++) {
        if (ch) { CPWAIT(0); __syncthreads(); }
        const __half* vs = ch ? vs1 : vs0;
        float oacc[4][4][4] = {};
#pragma unroll
        for (int kt = 0; kt < 16; kt++) {
            uint32_t aa[4][4];
#pragma unroll
            for (int qi = 0; qi < 4; qi++)
                ldmA(aa[qi], att, qg * 64 + qi * 16, kt * 16, lane, PSV);
            uint32_t b0[4], b1[4];
            ldmB2(b0, vs, og * 32, kt * 16, lane, PSV);
            ldmB2(b1, vs, og * 32 + 16, kt * 16, lane, PSV);
#pragma unroll
            for (int qi = 0; qi < 4; qi++) {
                mma16816(oacc[qi][0], aa[qi], b0);
                mma16816(oacc[qi][1], aa[qi], b0 + 2);
                mma16816(oacc[qi][2], aa[qi], b1);
                mma16816(oacc[qi][3], aa[qi], b1 + 2);
            }
        }
#pragma unroll
        for (int qi = 0; qi < 4; qi++) {
            int r0 = qg * 64 + qi * 16 + g;
            float rv0 = rsinv[r0], rv1 = rsinv[r0 + 8];
#pragma unroll
            for (int oi = 0; oi < 4; oi++) {
                int o = ch * 128 + og * 32 + oi * 8 + 2 * c;
                size_t i0 = (size_t)(b * 256 + o) * HWn + h * Wn + w0 + r0;
                out[i0]           = oacc[qi][oi][0] * rv0;
                out[i0 + HWn]     = oacc[qi][oi][1] * rv0;
                out[i0 + 8]       = oacc[qi][oi][2] * rv1;
                out[i0 + HWn + 8] = oacc[qi][oi][3] * rv1;
            }
        }
    }
}

// ---------------------------------------------------------------------------
extern "C" void kernel_launch(void* const* d_in, const int* in_sizes, int n_in,
                              void* d_out, int out_size)
{
    const float* flow   = (const float*)d_in[0];
    const float* de_out = (const float*)d_in[1];
    const float* Wq     = (const float*)d_in[2];
    const float* bq     = (const float*)d_in[3];
    const float* Wk     = (const float*)d_in[4];
    const float* bk     = (const float*)d_in[5];
    const float* Wv     = (const float*)d_in[6];
    const float* bv     = (const float*)d_in[7];
    float* out = (float*)d_out;

    cudaFuncSetAttribute(qk_proj, cudaFuncAttributeMaxDynamicSharedMemorySize, QK_SMEM);
    cudaFuncSetAttribute(v_proj,  cudaFuncAttributeMaxDynamicSharedMemorySize, V_SMEM);
    cudaFuncSetAttribute(attn,    cudaFuncAttributeMaxDynamicSharedMemorySize, A_SMEM);

    prep<<<192, 256>>>(Wq, Wk, Wv);
    qk_proj<<<dim3(HWn / 128, 2, Bn), 256, QK_SMEM>>>(de_out, flow, bq, bk);
    v_proj<<<dim3(HWn / 128, 1, Bn), 256, V_SMEM>>>(flow, bv);
    attn<<<dim3(Wn / 128, Hn, Bn), 256, A_SMEM>>>(out);
}

// round 15
// speedup vs baseline: 1.1362x; 1.0084x over previous
#include <cuda_runtime.h>
#include <cuda_fp16.h>
#include <cstdint>

#define Bn 4
#define Cn 256
#define Hn 128
#define Wn 256
#define HWn 32768
#define PS 72    // smem stride (halves), 64-wide tiles
#define PSV 264  // smem stride (halves), 256-wide rows

// q,k pre-split hi/lo fp16 [b][p][64]; v plain fp16 [b][o][p]
__device__ __half g_qh[(size_t)Bn * HWn * 64];
__device__ __half g_ql[(size_t)Bn * HWn * 64];
__device__ __half g_kh[(size_t)Bn * HWn * 64];
__device__ __half g_kl[(size_t)Bn * HWn * 64];
__device__ __half g_v [(size_t)Bn * 256 * HWn];
// pre-converted weights
__device__ __half g_wqh[64 * 256], g_wql[64 * 256];
__device__ __half g_wkh[64 * 256], g_wkl[64 * 256];
__device__ __half g_wv16[256 * 256];

// ---------------- helpers ----------------
static __device__ __forceinline__ void split2(float x, __half& h, __half& l) {
    h = __float2half_rn(x);
    l = __float2half_rn(x - __half2float(h));
}
static __device__ __forceinline__ uint32_t pack2(__half a, __half b) {
    __half2 t = __halves2half2(a, b);
    return *(uint32_t*)&t;
}
static __device__ __forceinline__ uint32_t sptr(const void* p) {
    return (uint32_t)__cvta_generic_to_shared(p);
}
static __device__ __forceinline__ void mma16816(float* d, const uint32_t* a, const uint32_t* b) {
    asm volatile("mma.sync.aligned.m16n8k16.row.col.f32.f16.f16.f32 "
        "{%0,%1,%2,%3}, {%4,%5,%6,%7}, {%8,%9}, {%0,%1,%2,%3};"
        : "+f"(d[0]), "+f"(d[1]), "+f"(d[2]), "+f"(d[3])
        : "r"(a[0]), "r"(a[1]), "r"(a[2]), "r"(a[3]), "r"(b[0]), "r"(b[1]));
}
static __device__ __forceinline__ void ldmA(uint32_t* a, const __half* t, int m0, int k0,
                                            int lane, int stride) {
    const __half* p = t + (m0 + (lane & 15)) * stride + k0 + ((lane >> 4) << 3);
    asm volatile("ldmatrix.sync.aligned.m8n8.x4.shared.b16 {%0,%1,%2,%3}, [%4];"
        : "=r"(a[0]), "=r"(a[1]), "=r"(a[2]), "=r"(a[3]) : "r"(sptr(p)));
}
static __device__ __forceinline__ void ldmB2(uint32_t* b, const __half* t, int n0, int k0,
                                             int lane, int stride) {
    int grp = lane >> 3;
    const __half* p = t + (n0 + ((grp & 2) << 2) + (lane & 7)) * stride + k0 + ((grp & 1) << 3);
    asm volatile("ldmatrix.sync.aligned.m8n8.x4.shared.b16 {%0,%1,%2,%3}, [%4];"
        : "=r"(b[0]), "=r"(b[1]), "=r"(b[2]), "=r"(b[3]) : "r"(sptr(p)));
}
#define CP16(d, s)  asm volatile("cp.async.cg.shared.global [%0], [%1], 16;" :: "r"(d), "l"(s))
#define CPCOMMIT()  asm volatile("cp.async.commit_group;")
#define CPWAIT(n)   asm volatile("cp.async.wait_group %0;" :: "n"(n) : "memory")

// ---------------------------------------------------------------------------
// prep: Wq/Wk -> hi/lo fp16, Wv -> fp16
// ---------------------------------------------------------------------------
__global__ void prep(const float* __restrict__ Wq, const float* __restrict__ Wk,
                     const float* __restrict__ Wv)
{
    int i = (blockIdx.x * 256 + threadIdx.x) * 2;
    __half h0, l0, h1, l1;
    if (i < 16384) {
        split2(Wq[i], h0, l0); split2(Wq[i + 1], h1, l1);
        *(uint32_t*)&g_wqh[i] = pack2(h0, h1);
        *(uint32_t*)&g_wql[i] = pack2(l0, l1);
    } else if (i < 32768) {
        int j = i - 16384;
        split2(Wk[j], h0, l0); split2(Wk[j + 1], h1, l1);
        *(uint32_t*)&g_wkh[j] = pack2(h0, h1);
        *(uint32_t*)&g_wkl[j] = pack2(l0, l1);
    } else {
        int j = i - 32768;
        *(uint32_t*)&g_wv16[j] = pack2(__float2half_rn(Wv[j]), __float2half_rn(Wv[j + 1]));
    }
}

// ---------------------------------------------------------------------------
// megaproj v2: blockIdx.x selects path. 0=q, 1=k (3-term split, 128p x 64d),
// 2/3 = v o-half (1-term, 128p x 128o). 256 threads, 73728 B smem.
// launch_bounds(256,2): 128-reg budget -> NO SPILLS (R13's failure), 2 blk/SM
// (2 warps/SMSP saturates HMMA issue per attn evidence). x fastest dispatch
// -> k/v blocks of same tile share flow via L2; type mixing hides staging.
// ---------------------------------------------------------------------------
#define MP_SMEM 73728
__global__ __launch_bounds__(256, 2) void megaproj(
    const float* __restrict__ de_out, const float* __restrict__ flow,
    const float* __restrict__ bq, const float* __restrict__ bk,
    const float* __restrict__ bv)
{
    extern __shared__ __half smh[];
    const int tid = threadIdx.x, w = tid >> 5, lane = tid & 31;
    const int c = lane & 3, g = lane >> 2;
    const int wm = w & 3, wn = w >> 2;
    const int type = blockIdx.x;
    const int p0 = blockIdx.y * 128, b = blockIdx.z;

    if (type < 2) {
        // ---------------- q/k path (3-term split) ----------------
        const int isK = type;
        __half* xh = smh;
        __half* xl = smh + 9216;

        const float*  X    = isK ? flow : de_out;
        const float*  bias = isK ? bk : bq;
        const __half* wsh  = isK ? g_wkh : g_wqh;
        const __half* wsl  = isK ? g_wkl : g_wql;
        __half*       Yh   = isK ? g_kh : g_qh;
        __half*       Yl   = isK ? g_kl : g_ql;
        const float* Xb = X + (size_t)b * Cn * HWn;

        float acc[2][4][4] = {};

        {
            __half* wb = smh + 18432;
            for (int i = tid; i < 512; i += 256) {
                int d = i >> 3, s = (i & 7) * 8;
                CP16(sptr(wb + d * PS + s), wsh + d * 256 + s);
                CP16(sptr(wb + 4608 + d * PS + s), wsl + d * 256 + s);
            }
            CPCOMMIT();
        }

        for (int kc = 0; kc < 4; kc++) {
            if (kc < 3) {
                __half* wb = smh + 18432 + ((kc + 1) & 1) * 9216;
                for (int i = tid; i < 512; i += 256) {
                    int d = i >> 3, s = (i & 7) * 8;
                    CP16(sptr(wb + d * PS + s), wsh + d * 256 + (kc + 1) * 64 + s);
                    CP16(sptr(wb + 4608 + d * PS + s), wsl + d * 256 + (kc + 1) * 64 + s);
                }
                CPCOMMIT();
            }
            for (int i = tid; i < 2048; i += 256) {
                int p = i & 127, cg = i >> 7;
                const float* src = &Xb[(size_t)(kc * 64 + cg * 4) * HWn + p0 + p];
                __half h0, l0, h1, l1;
                uint2 hv, lv;
                split2(src[0], h0, l0);
                split2(src[(size_t)HWn], h1, l1);
                hv.x = pack2(h0, h1); lv.x = pack2(l0, l1);
                split2(src[2 * (size_t)HWn], h0, l0);
                split2(src[3 * (size_t)HWn], h1, l1);
                hv.y = pack2(h0, h1); lv.y = pack2(l0, l1);
                *(uint2*)&xh[p * PS + cg * 4] = hv;
                *(uint2*)&xl[p * PS + cg * 4] = lv;
            }
            if (kc < 3) CPWAIT(1); else CPWAIT(0);
            __syncthreads();

            const __half* wh = smh + 18432 + (kc & 1) * 9216;
            const __half* wl = wh + 4608;
#pragma unroll
            for (int kt = 0; kt < 4; kt++) {
                uint32_t ah0[4], al0[4], ah1[4], al1[4];
                ldmA(ah0, xh, wm * 32, kt * 16, lane, PS);
                ldmA(al0, xl, wm * 32, kt * 16, lane, PS);
                ldmA(ah1, xh, wm * 32 + 16, kt * 16, lane, PS);
                ldmA(al1, xl, wm * 32 + 16, kt * 16, lane, PS);
#pragma unroll
                for (int nt = 0; nt < 4; nt += 2) {
                    uint32_t bh[4], bl[4];
                    ldmB2(bh, wh, wn * 32 + nt * 8, kt * 16, lane, PS);
                    ldmB2(bl, wl, wn * 32 + nt * 8, kt * 16, lane, PS);
                    mma16816(acc[0][nt], ah0, bh);
                    mma16816(acc[0][nt], ah0, bl);
                    mma16816(acc[0][nt], al0, bh);
                    mma16816(acc[1][nt], ah1, bh);
                    mma16816(acc[1][nt], ah1, bl);
                    mma16816(acc[1][nt], al1, bh);
                    mma16816(acc[0][nt + 1], ah0, bh + 2);
                    mma16816(acc[0][nt + 1], ah0, bl + 2);
                    mma16816(acc[0][nt + 1], al0, bh + 2);
                    mma16816(acc[1][nt + 1], ah1, bh + 2);
                    mma16816(acc[1][nt + 1], ah1, bl + 2);
                    mma16816(acc[1][nt + 1], al1, bh + 2);
                }
            }
            __syncthreads();
        }
#pragma unroll
        for (int mt = 0; mt < 2; mt++) {
#pragma unroll
            for (int nt = 0; nt < 4; nt++) {
                int dcol = wn * 32 + nt * 8 + 2 * c;
                float b0 = bias[dcol], b1 = bias[dcol + 1];
                size_t r0 = ((size_t)b * HWn + p0 + wm * 32 + mt * 16 + g) * 64 + dcol;
                size_t r1 = r0 + (size_t)8 * 64;
                __half h0, l0, h1, l1;
                split2(acc[mt][nt][0] + b0, h0, l0);
                split2(acc[mt][nt][1] + b1, h1, l1);
                *(uint32_t*)&Yh[r0] = pack2(h0, h1);
                *(uint32_t*)&Yl[r0] = pack2(l0, l1);
                split2(acc[mt][nt][2] + b0, h0, l0);
                split2(acc[mt][nt][3] + b1, h1, l1);
                *(uint32_t*)&Yh[r1] = pack2(h0, h1);
                *(uint32_t*)&Yl[r1] = pack2(l0, l1);
            }
        }
    } else {
        // ---------------- v path (1-term, o-half per block) ----------------
        const int ohalf = type - 2;
        __half* xs = smh;                          // [128 p][72] hi only
        const float* Xb = flow + (size_t)b * Cn * HWn;
        const __half* wsrc = g_wv16 + (size_t)(ohalf * 128) * 256;

        // issue W chunk 0 ([128 o][64 c])
        {
            __half* wb = smh + 18432;
            for (int i = tid; i < 1024; i += 256) {
                int o = i >> 3, s = (i & 7) * 8;
                CP16(sptr(wb + o * PS + s), wsrc + o * 256 + s);
            }
            CPCOMMIT();
        }

        float acc[2][8][4] = {};

        for (int kc = 0; kc < 4; kc++) {
            if (kc < 3) {
                __half* wb = smh + 18432 + ((kc + 1) & 1) * 9216;
                for (int i = tid; i < 1024; i += 256) {
                    int o = i >> 3, s = (i & 7) * 8;
                    CP16(sptr(wb + o * PS + s), wsrc + o * 256 + (kc + 1) * 64 + s);
                }
                CPCOMMIT();
            }
            // stage X hi chunk [128 p][64 c]
            for (int i = tid; i < 2048; i += 256) {
                int p = i & 127, cg = i >> 7;
                const float* src = &Xb[(size_t)(kc * 64 + cg * 4) * HWn + p0 + p];
                uint2 hv;
                hv.x = pack2(__float2half_rn(src[0]), __float2half_rn(src[(size_t)HWn]));
                hv.y = pack2(__float2half_rn(src[2 * (size_t)HWn]),
                             __float2half_rn(src[3 * (size_t)HWn]));
                *(uint2*)&xs[p * PS + cg * 4] = hv;
            }
            if (kc < 3) CPWAIT(1); else CPWAIT(0);
            __syncthreads();

            const __half* wb = smh + 18432 + (kc & 1) * 9216;
#pragma unroll
            for (int kt = 0; kt < 4; kt++) {
                uint32_t a0[4], a1[4];
                ldmA(a0, xs, wm * 32, kt * 16, lane, PS);
                ldmA(a1, xs, wm * 32 + 16, kt * 16, lane, PS);
#pragma unroll
                for (int ntp = 0; ntp < 4; ntp++) {
                    uint32_t bb[4];
                    ldmB2(bb, wb, wn * 64 + ntp * 16, kt * 16, lane, PS);
                    mma16816(acc[0][2 * ntp], a0, bb);
                    mma16816(acc[1][2 * ntp], a1, bb);
                    mma16816(acc[0][2 * ntp + 1], a0, bb + 2);
                    mma16816(acc[1][2 * ntp + 1], a1, bb + 2);
                }
            }
            __syncthreads();
        }
#pragma unroll
        for (int mt = 0; mt < 2; mt++) {
#pragma unroll
            for (int nt = 0; nt < 8; nt++) {
                int o = ohalf * 128 + wn * 64 + nt * 8 + 2 * c;
                int p = p0 + wm * 32 + mt * 16 + g;
                float b0 = bv[o], b1 = bv[o + 1];
                g_v[(size_t)(b * 256 + o) * HWn + p]         = __float2half_rn(acc[mt][nt][0] + b0);
                g_v[(size_t)(b * 256 + o + 1) * HWn + p]     = __float2half_rn(acc[mt][nt][1] + b1);
                g_v[(size_t)(b * 256 + o) * HWn + p + 8]     = __float2half_rn(acc[mt][nt][2] + b0);
                g_v[(size_t)(b * 256 + o + 1) * HWn + p + 8] = __float2half_rn(acc[mt][nt][3] + b1);
            }
        }
    }
}

// ---------------------------------------------------------------------------
// Fused attention (R10 v1, at HMMA-issue floor): E (3-term) -> warp softmax
// -> AV (1-term). grid (2, 128, B), 256 threads.
// ---------------------------------------------------------------------------
#define A_SMEM (110592 + 67584)
__global__ __launch_bounds__(256, 1) void attn(float* __restrict__ out)
{
    extern __shared__ __half smh[];
    __half* qh = smh;
    __half* ql = qh + 128 * PS;
    __half* kh = ql + 128 * PS;
    __half* kl = kh + 256 * PS;
    __half* vs0 = smh + 55296;
    __half* vs1 = smh;

    const int tid = threadIdx.x, w = tid >> 5, lane = tid & 31;
    const int c = lane & 3, g = lane >> 2;
    const int qt = blockIdx.x, h = blockIdx.y, b = blockIdx.z;
    const int w0 = qt * 128;
    const __half* vg = g_v + (size_t)b * 256 * HWn + h * Wn;

    {
        const __half* qsh = g_qh + ((size_t)b * HWn + h * Wn + w0) * 64;
        const __half* qsl = g_ql + ((size_t)b * HWn + h * Wn + w0) * 64;
        const __half* ksh = g_kh + ((size_t)b * HWn + h * Wn) * 64;
        const __half* ksl = g_kl + ((size_t)b * HWn + h * Wn) * 64;
        for (int i = tid; i < 1024; i += 256) {
            int r = i >> 3, s = (i & 7) * 8;
            CP16(sptr(qh + r * PS + s), qsh + r * 64 + s);
            CP16(sptr(ql + r * PS + s), qsl + r * 64 + s);
        }
        for (int i = tid; i < 2048; i += 256) {
            int r = i >> 3, s = (i & 7) * 8;
            CP16(sptr(kh + r * PS + s), ksh + r * 64 + s);
            CP16(sptr(kl + r * PS + s), ksl + r * 64 + s);
        }
        CPCOMMIT();
    }
    for (int i = tid; i < 4096; i += 256) {
        int o = i >> 5, s = (i & 31) * 8;
        CP16(sptr(vs0 + o * PSV + s), vg + (size_t)o * HWn + s);
    }
    CPCOMMIT();

    CPWAIT(1);
    __syncthreads();

    float e[32][4] = {};
#pragma unroll
    for (int kt = 0; kt < 4; kt++) {
        uint32_t ah[4], al[4];
        ldmA(ah, qh, w * 16, kt * 16, lane, PS);
        ldmA(al, ql, w * 16, kt * 16, lane, PS);
#pragma unroll
        for (int nt = 0; nt < 32; nt += 2) {
            uint32_t bh[4], bl[4];
            ldmB2(bh, kh, nt * 8, kt * 16, lane, PS);
            ldmB2(bl, kl, nt * 8, kt * 16, lane, PS);
            mma16816(e[nt], ah, bh);
            mma16816(e[nt], ah, bl);
            mma16816(e[nt], al, bh);
            mma16816(e[nt + 1], ah, bh + 2);
            mma16816(e[nt + 1], ah, bl + 2);
            mma16816(e[nt + 1], al, bh + 2);
        }
    }
    __syncthreads();

    for (int i = tid; i < 4096; i += 256) {
        int o = i >> 5, s = (i & 31) * 8;
        CP16(sptr(vs1 + o * PSV + s), vg + (size_t)(o + 128) * HWn + s);
    }
    CPCOMMIT();

    float m0 = -1e30f, m1 = -1e30f;
#pragma unroll
    for (int nt = 0; nt < 32; nt++) {
        m0 = fmaxf(m0, fmaxf(e[nt][0], e[nt][1]));
        m1 = fmaxf(m1, fmaxf(e[nt][2], e[nt][3]));
    }
    m0 = fmaxf(m0, __shfl_xor_sync(0xffffffffu, m0, 1));
    m0 = fmaxf(m0, __shfl_xor_sync(0xffffffffu, m0, 2));
    m1 = fmaxf(m1, __shfl_xor_sync(0xffffffffu, m1, 1));
    m1 = fmaxf(m1, __shfl_xor_sync(0xffffffffu, m1, 2));

    float s0 = 0.f, s1 = 0.f;
    uint32_t ah_[64];
#pragma unroll
    for (int nt = 0; nt < 32; nt++) {
        float p00 = __expf(e[nt][0] - m0), p01 = __expf(e[nt][1] - m0);
        float p10 = __expf(e[nt][2] - m1), p11 = __expf(e[nt][3] - m1);
        s0 += p00 + p01;
        s1 += p10 + p11;
        ah_[2 * nt]     = pack2(__float2half_rn(p00), __float2half_rn(p01));
        ah_[2 * nt + 1] = pack2(__float2half_rn(p10), __float2half_rn(p11));
    }
    s0 += __shfl_xor_sync(0xffffffffu, s0, 1);
    s0 += __shfl_xor_sync(0xffffffffu, s0, 2);
    s1 += __shfl_xor_sync(0xffffffffu, s1, 1);
    s1 += __shfl_xor_sync(0xffffffffu, s1, 2);
    const float rinv0 = 1.0f / s0, rinv1 = 1.0f / s1;

    CPWAIT(1);
    __syncthreads();
    {
        float oacc[16][4] = {};
#pragma unroll
        for (int kt = 0; kt < 16; kt++) {
            const uint32_t* Ah = &ah_[4 * kt];
#pragma unroll
            for (int nt = 0; nt < 16; nt += 2) {
                uint32_t bb[4];
                ldmB2(bb, vs0, nt * 8, kt * 16, lane, PSV);
                mma16816(oacc[nt], Ah, bb);
                mma16816(oacc[nt + 1], Ah, bb + 2);
            }
        }
#pragma unroll
        for (int nt = 0; nt < 16; nt++) {
            int o = nt * 8 + 2 * c;
            size_t i0 = (size_t)(b * 256 + o) * HWn + h * Wn + w0 + w * 16 + g;
            out[i0]           = oacc[nt][0] * rinv0;
            out[i0 + HWn]     = oacc[nt][1] * rinv0;
            out[i0 + 8]       = oacc[nt][2] * rinv1;
            out[i0 + HWn + 8] = oacc[nt][3] * rinv1;
        }
    }

    CPWAIT(0);
    __syncthreads();
    {
        float oacc[16][4] = {};
#pragma unroll
        for (int kt = 0; kt < 16; kt++) {
            const uint32_t* Ah = &ah_[4 * kt];
#pragma unroll
            for (int nt = 0; nt < 16; nt += 2) {
                uint32_t bb[4];
                ldmB2(bb, vs1, nt * 8, kt * 16, lane, PSV);
                mma16816(oacc[nt], Ah, bb);
                mma16816(oacc[nt + 1], Ah, bb + 2);
            }
        }
#pragma unroll
        for (int nt = 0; nt < 16; nt++) {
            int o = 128 + nt * 8 + 2 * c;
            size_t i0 = (size_t)(b * 256 + o) * HWn + h * Wn + w0 + w * 16 + g;
            out[i0]           = oacc[nt][0] * rinv0;
            out[i0 + HWn]     = oacc[nt][1] * rinv0;
            out[i0 + 8]       = oacc[nt][2] * rinv1;
            out[i0 + HWn + 8] = oacc[nt][3] * rinv1;
        }
    }
}

// ---------------------------------------------------------------------------
extern "C" void kernel_launch(void* const* d_in, const int* in_sizes, int n_in,
                              void* d_out, int out_size)
{
    const float* flow   = (const float*)d_in[0];
    const float* de_out = (const float*)d_in[1];
    const float* Wq     = (const float*)d_in[2];
    const float* bq     = (const float*)d_in[3];
    const float* Wk     = (const float*)d_in[4];
    const float* bk     = (const float*)d_in[5];
    const float* Wv     = (const float*)d_in[6];
    const float* bv     = (const float*)d_in[7];
    float* out = (float*)d_out;

    cudaFuncSetAttribute(megaproj, cudaFuncAttributeMaxDynamicSharedMemorySize, MP_SMEM);
    cudaFuncSetAttribute(attn,     cudaFuncAttributeMaxDynamicSharedMemorySize, A_SMEM);

    prep<<<192, 256>>>(Wq, Wk, Wv);
    megaproj<<<dim3(4, HWn / 128, Bn), 256, MP_SMEM>>>(de_out, flow, bq, bk, bv);
    attn<<<dim3(Wn / 128, Hn, Bn), 256, A_SMEM>>>(out);
}

// round 17
// speedup vs baseline: 1.2142x; 1.0686x over previous
#include <cuda_runtime.h>
#include <cuda_fp16.h>
#include <cstdint>

#define Bn 4
#define Cn 256
#define Hn 128
#define Wn 256
#define HWn 32768
#define PS 72    // smem stride (halves), 64-wide tiles
#define PSV 264  // smem stride (halves), 256-wide rows

// q,k pre-split hi/lo fp16 [b][p][64]; v plain fp16 [b][o][p]
__device__ __half g_qh[(size_t)Bn * HWn * 64];
__device__ __half g_ql[(size_t)Bn * HWn * 64];
__device__ __half g_kh[(size_t)Bn * HWn * 64];
__device__ __half g_kl[(size_t)Bn * HWn * 64];
__device__ __half g_v [(size_t)Bn * 256 * HWn];
// pre-converted weights
__device__ __half g_wqh[64 * 256], g_wql[64 * 256];
__device__ __half g_wkh[64 * 256], g_wkl[64 * 256];
__device__ __half g_wv16[256 * 256];

// ---------------- helpers ----------------
static __device__ __forceinline__ void split2(float x, __half& h, __half& l) {
    h = __float2half_rn(x);
    l = __float2half_rn(x - __half2float(h));
}
static __device__ __forceinline__ uint32_t pack2(__half a, __half b) {
    __half2 t = __halves2half2(a, b);
    return *(uint32_t*)&t;
}
static __device__ __forceinline__ uint32_t sptr(const void* p) {
    return (uint32_t)__cvta_generic_to_shared(p);
}
static __device__ __forceinline__ void mma16816(float* d, const uint32_t* a, const uint32_t* b) {
    asm volatile("mma.sync.aligned.m16n8k16.row.col.f32.f16.f16.f32 "
        "{%0,%1,%2,%3}, {%4,%5,%6,%7}, {%8,%9}, {%0,%1,%2,%3};"
        : "+f"(d[0]), "+f"(d[1]), "+f"(d[2]), "+f"(d[3])
        : "r"(a[0]), "r"(a[1]), "r"(a[2]), "r"(a[3]), "r"(b[0]), "r"(b[1]));
}
static __device__ __forceinline__ void ldmA(uint32_t* a, const __half* t, int m0, int k0,
                                            int lane, int stride) {
    const __half* p = t + (m0 + (lane & 15)) * stride + k0 + ((lane >> 4) << 3);
    asm volatile("ldmatrix.sync.aligned.m8n8.x4.shared.b16 {%0,%1,%2,%3}, [%4];"
        : "=r"(a[0]), "=r"(a[1]), "=r"(a[2]), "=r"(a[3]) : "r"(sptr(p)));
}
static __device__ __forceinline__ void ldmB2(uint32_t* b, const __half* t, int n0, int k0,
                                             int lane, int stride) {
    int grp = lane >> 3;
    const __half* p = t + (n0 + ((grp & 2) << 2) + (lane & 7)) * stride + k0 + ((grp & 1) << 3);
    asm volatile("ldmatrix.sync.aligned.m8n8.x4.shared.b16 {%0,%1,%2,%3}, [%4];"
        : "=r"(b[0]), "=r"(b[1]), "=r"(b[2]), "=r"(b[3]) : "r"(sptr(p)));
}
#define CP16(d, s)  asm volatile("cp.async.cg.shared.global [%0], [%1], 16;" :: "r"(d), "l"(s))
#define CPCOMMIT()  asm volatile("cp.async.commit_group;")
#define CPWAIT(n)   asm volatile("cp.async.wait_group %0;" :: "n"(n) : "memory")

// ---------------------------------------------------------------------------
// prep: Wq/Wk -> hi/lo fp16, Wv -> fp16
// ---------------------------------------------------------------------------
__global__ void prep(const float* __restrict__ Wq, const float* __restrict__ Wk,
                     const float* __restrict__ Wv)
{
    int i = (blockIdx.x * 256 + threadIdx.x) * 2;
    __half h0, l0, h1, l1;
    if (i < 16384) {
        split2(Wq[i], h0, l0); split2(Wq[i + 1], h1, l1);
        *(uint32_t*)&g_wqh[i] = pack2(h0, h1);
        *(uint32_t*)&g_wql[i] = pack2(l0, l1);
    } else if (i < 32768) {
        int j = i - 16384;
        split2(Wk[j], h0, l0); split2(Wk[j + 1], h1, l1);
        *(uint32_t*)&g_wkh[j] = pack2(h0, h1);
        *(uint32_t*)&g_wkl[j] = pack2(l0, l1);
    } else {
        int j = i - 32768;
        *(uint32_t*)&g_wv16[j] = pack2(__float2half_rn(Wv[j]), __float2half_rn(Wv[j + 1]));
    }
}

// ---------------------------------------------------------------------------
// megaproj v4: blockIdx.x selects path (0=q, 1=k 3-term; 2/3 = v o-half
// 1-term). 256 threads, 110592 B smem, 2 blk/SM.
// X register-prefetched across MMA; ONE sync per chunk. RACE FIX vs v3:
// W(kc+1) cp.async is issued AFTER the barrier, so it can never overwrite
// a W buffer still being read by a slower warp's MMA(kc-1).
// Per-chunk order: store X(kc) -> CPWAIT -> sync -> issue W(kc+1)
//                  -> prefetch X(kc+1) -> MMA(kc).
// ---------------------------------------------------------------------------
#define MP_SMEM 110592
__global__ __launch_bounds__(256, 2) void megaproj(
    const float* __restrict__ de_out, const float* __restrict__ flow,
    const float* __restrict__ bq, const float* __restrict__ bk,
    const float* __restrict__ bv)
{
    extern __shared__ __half smh[];
    const int tid = threadIdx.x, w = tid >> 5, lane = tid & 31;
    const int c = lane & 3, g = lane >> 2;
    const int wm = w & 3, wn = w >> 2;
    const int type = blockIdx.x;
    const int p0 = blockIdx.y * 128, b = blockIdx.z;
    const int px = tid & 127, cg0 = tid >> 7;   // staging coords

    if (type < 2) {
        // ---------------- q/k path (3-term split) ----------------
        const int isK = type;
        const float*  X    = isK ? flow : de_out;
        const float*  bias = isK ? bk : bq;
        const __half* wsh  = isK ? g_wkh : g_wqh;
        const __half* wsl  = isK ? g_wkl : g_wql;
        __half*       Yh   = isK ? g_kh : g_qh;
        __half*       Yl   = isK ? g_kl : g_ql;
        const float* Xb = X + (size_t)b * Cn * HWn;

        float acc[2][4][4] = {};
        float pf[8][4];

        // prologue: prefetch X chunk 0; issue W chunk 0
#pragma unroll
        for (int j = 0; j < 8; j++) {
            const float* s = Xb + (size_t)(cg0 * 4 + 8 * j) * HWn + p0 + px;
            pf[j][0] = s[0];
            pf[j][1] = s[(size_t)HWn];
            pf[j][2] = s[2 * (size_t)HWn];
            pf[j][3] = s[3 * (size_t)HWn];
        }
        {
            __half* wb = smh + 36864;
            for (int i = tid; i < 512; i += 256) {
                int d = i >> 3, s = (i & 7) * 8;
                CP16(sptr(wb + d * PS + s), wsh + d * 256 + s);
                CP16(sptr(wb + 4608 + d * PS + s), wsl + d * 256 + s);
            }
            CPCOMMIT();
        }

        for (int kc = 0; kc < 4; kc++) {
            // store prefetched X -> buf[kc&1]
            __half* xh = smh + (kc & 1) * 18432;
            __half* xl = xh + 9216;
#pragma unroll
            for (int j = 0; j < 8; j++) {
                int cg = cg0 + 2 * j;
                __half h0, l0, h1, l1;
                uint2 hv, lv;
                split2(pf[j][0], h0, l0);
                split2(pf[j][1], h1, l1);
                hv.x = pack2(h0, h1); lv.x = pack2(l0, l1);
                split2(pf[j][2], h0, l0);
                split2(pf[j][3], h1, l1);
                hv.y = pack2(h0, h1); lv.y = pack2(l0, l1);
                *(uint2*)&xh[px * PS + cg * 4] = hv;
                *(uint2*)&xl[px * PS + cg * 4] = lv;
            }
            CPWAIT(0);          // W(kc) arrived (only group in flight)
            __syncthreads();    // X stores visible; MMA(kc-1) complete

            if (kc < 3) {       // SAFE: issue W(kc+1) after barrier
                __half* wb = smh + 36864 + ((kc + 1) & 1) * 9216;
                for (int i = tid; i < 512; i += 256) {
                    int d = i >> 3, s = (i & 7) * 8;
                    CP16(sptr(wb + d * PS + s), wsh + d * 256 + (kc + 1) * 64 + s);
                    CP16(sptr(wb + 4608 + d * PS + s), wsl + d * 256 + (kc + 1) * 64 + s);
                }
                CPCOMMIT();
                // prefetch X chunk kc+1 (LDGs overlap MMA below)
#pragma unroll
                for (int j = 0; j < 8; j++) {
                    const float* s = Xb + (size_t)((kc + 1) * 64 + cg0 * 4 + 8 * j) * HWn + p0 + px;
                    pf[j][0] = s[0];
                    pf[j][1] = s[(size_t)HWn];
                    pf[j][2] = s[2 * (size_t)HWn];
                    pf[j][3] = s[3 * (size_t)HWn];
                }
            }
            const __half* wh = smh + 36864 + (kc & 1) * 9216;
            const __half* wl = wh + 4608;
#pragma unroll
            for (int kt = 0; kt < 4; kt++) {
                uint32_t ah0[4], al0[4], ah1[4], al1[4];
                ldmA(ah0, xh, wm * 32, kt * 16, lane, PS);
                ldmA(al0, xl, wm * 32, kt * 16, lane, PS);
                ldmA(ah1, xh, wm * 32 + 16, kt * 16, lane, PS);
                ldmA(al1, xl, wm * 32 + 16, kt * 16, lane, PS);
#pragma unroll
                for (int nt = 0; nt < 4; nt += 2) {
                    uint32_t bh[4], bl[4];
                    ldmB2(bh, wh, wn * 32 + nt * 8, kt * 16, lane, PS);
                    ldmB2(bl, wl, wn * 32 + nt * 8, kt * 16, lane, PS);
                    mma16816(acc[0][nt], ah0, bh);
                    mma16816(acc[0][nt], ah0, bl);
                    mma16816(acc[0][nt], al0, bh);
                    mma16816(acc[1][nt], ah1, bh);
                    mma16816(acc[1][nt], ah1, bl);
                    mma16816(acc[1][nt], al1, bh);
                    mma16816(acc[0][nt + 1], ah0, bh + 2);
                    mma16816(acc[0][nt + 1], ah0, bl + 2);
                    mma16816(acc[0][nt + 1], al0, bh + 2);
                    mma16816(acc[1][nt + 1], ah1, bh + 2);
                    mma16816(acc[1][nt + 1], ah1, bl + 2);
                    mma16816(acc[1][nt + 1], al1, bh + 2);
                }
            }
        }
#pragma unroll
        for (int mt = 0; mt < 2; mt++) {
#pragma unroll
            for (int nt = 0; nt < 4; nt++) {
                int dcol = wn * 32 + nt * 8 + 2 * c;
                float b0 = bias[dcol], b1 = bias[dcol + 1];
                size_t r0 = ((size_t)b * HWn + p0 + wm * 32 + mt * 16 + g) * 64 + dcol;
                size_t r1 = r0 + (size_t)8 * 64;
                __half h0, l0, h1, l1;
                split2(acc[mt][nt][0] + b0, h0, l0);
                split2(acc[mt][nt][1] + b1, h1, l1);
                *(uint32_t*)&Yh[r0] = pack2(h0, h1);
                *(uint32_t*)&Yl[r0] = pack2(l0, l1);
                split2(acc[mt][nt][2] + b0, h0, l0);
                split2(acc[mt][nt][3] + b1, h1, l1);
                *(uint32_t*)&Yh[r1] = pack2(h0, h1);
                *(uint32_t*)&Yl[r1] = pack2(l0, l1);
            }
        }
    } else {
        // ---------------- v path (1-term, o-half per block) ----------------
        const int ohalf = type - 2;
        const float* Xb = flow + (size_t)b * Cn * HWn;
        const __half* wsrc = g_wv16 + (size_t)(ohalf * 128) * 256;

        float acc[2][8][4] = {};
        float pf[8][4];

        // prologue: prefetch X chunk 0; issue W chunk 0
#pragma unroll
        for (int j = 0; j < 8; j++) {
            const float* s = Xb + (size_t)(cg0 * 4 + 8 * j) * HWn + p0 + px;
            pf[j][0] = s[0];
            pf[j][1] = s[(size_t)HWn];
            pf[j][2] = s[2 * (size_t)HWn];
            pf[j][3] = s[3 * (size_t)HWn];
        }
        {
            __half* wb = smh + 18432;
            for (int i = tid; i < 1024; i += 256) {
                int o = i >> 3, s = (i & 7) * 8;
                CP16(sptr(wb + o * PS + s), wsrc + o * 256 + s);
            }
            CPCOMMIT();
        }

        for (int kc = 0; kc < 4; kc++) {
            __half* xs = smh + (kc & 1) * 9216;
#pragma unroll
            for (int j = 0; j < 8; j++) {
                int cg = cg0 + 2 * j;
                uint2 hv;
                hv.x = pack2(__float2half_rn(pf[j][0]), __float2half_rn(pf[j][1]));
                hv.y = pack2(__float2half_rn(pf[j][2]), __float2half_rn(pf[j][3]));
                *(uint2*)&xs[px * PS + cg * 4] = hv;
            }
            CPWAIT(0);
            __syncthreads();

            if (kc < 3) {       // SAFE: issue W(kc+1) after barrier
                __half* wb = smh + 18432 + ((kc + 1) & 1) * 9216;
                for (int i = tid; i < 1024; i += 256) {
                    int o = i >> 3, s = (i & 7) * 8;
                    CP16(sptr(wb + o * PS + s), wsrc + o * 256 + (kc + 1) * 64 + s);
                }
                CPCOMMIT();
#pragma unroll
                for (int j = 0; j < 8; j++) {
                    const float* s = Xb + (size_t)((kc + 1) * 64 + cg0 * 4 + 8 * j) * HWn + p0 + px;
                    pf[j][0] = s[0];
                    pf[j][1] = s[(size_t)HWn];
                    pf[j][2] = s[2 * (size_t)HWn];
                    pf[j][3] = s[3 * (size_t)HWn];
                }
            }
            const __half* wb = smh + 18432 + (kc & 1) * 9216;
#pragma unroll
            for (int kt = 0; kt < 4; kt++) {
                uint32_t a0[4], a1[4];
                ldmA(a0, xs, wm * 32, kt * 16, lane, PS);
                ldmA(a1, xs, wm * 32 + 16, kt * 16, lane, PS);
#pragma unroll
                for (int ntp = 0; ntp < 4; ntp++) {
                    uint32_t bb[4];
                    ldmB2(bb, wb, wn * 64 + ntp * 16, kt * 16, lane, PS);
                    mma16816(acc[0][2 * ntp], a0, bb);
                    mma16816(acc[1][2 * ntp], a1, bb);
                    mma16816(acc[0][2 * ntp + 1], a0, bb + 2);
                    mma16816(acc[1][2 * ntp + 1], a1, bb + 2);
                }
            }
        }
#pragma unroll
        for (int mt = 0; mt < 2; mt++) {
#pragma unroll
            for (int nt = 0; nt < 8; nt++) {
                int o = ohalf * 128 + wn * 64 + nt * 8 + 2 * c;
                int p = p0 + wm * 32 + mt * 16 + g;
                float b0 = bv[o], b1 = bv[o + 1];
                g_v[(size_t)(b * 256 + o) * HWn + p]         = __float2half_rn(acc[mt][nt][0] + b0);
                g_v[(size_t)(b * 256 + o + 1) * HWn + p]     = __float2half_rn(acc[mt][nt][1] + b1);
                g_v[(size_t)(b * 256 + o) * HWn + p + 8]     = __float2half_rn(acc[mt][nt][2] + b0);
                g_v[(size_t)(b * 256 + o + 1) * HWn + p + 8] = __float2half_rn(acc[mt][nt][3] + b1);
            }
        }
    }
}

// ---------------------------------------------------------------------------
// Fused attention (R10 v1, at HMMA-issue floor): E (3-term) -> warp softmax
// -> AV (1-term). grid (2, 128, B), 256 threads. UNCHANGED.
// ---------------------------------------------------------------------------
#define A_SMEM (110592 + 67584)
__global__ __launch_bounds__(256, 1) void attn(float* __restrict__ out)
{
    extern __shared__ __half smh[];
    __half* qh = smh;
    __half* ql = qh + 128 * PS;
    __half* kh = ql + 128 * PS;
    __half* kl = kh + 256 * PS;
    __half* vs0 = smh + 55296;
    __half* vs1 = smh;

    const int tid = threadIdx.x, w = tid >> 5, lane = tid & 31;
    const int c = lane & 3, g = lane >> 2;
    const int qt = blockIdx.x, h = blockIdx.y, b = blockIdx.z;
    const int w0 = qt * 128;
    const __half* vg = g_v + (size_t)b * 256 * HWn + h * Wn;

    {
        const __half* qsh = g_qh + ((size_t)b * HWn + h * Wn + w0) * 64;
        const __half* qsl = g_ql + ((size_t)b * HWn + h * Wn + w0) * 64;
        const __half* ksh = g_kh + ((size_t)b * HWn + h * Wn) * 64;
        const __half* ksl = g_kl + ((size_t)b * HWn + h * Wn) * 64;
        for (int i = tid; i < 1024; i += 256) {
            int r = i >> 3, s = (i & 7) * 8;
            CP16(sptr(qh + r * PS + s), qsh + r * 64 + s);
            CP16(sptr(ql + r * PS + s), qsl + r * 64 + s);
        }
        for (int i = tid; i < 2048; i += 256) {
            int r = i >> 3, s = (i & 7) * 8;
            CP16(sptr(kh + r * PS + s), ksh + r * 64 + s);
            CP16(sptr(kl + r * PS + s), ksl + r * 64 + s);
        }
        CPCOMMIT();
    }
    for (int i = tid; i < 4096; i += 256) {
        int o = i >> 5, s = (i & 31) * 8;
        CP16(sptr(vs0 + o * PSV + s), vg + (size_t)o * HWn + s);
    }
    CPCOMMIT();

    CPWAIT(1);
    __syncthreads();

    float e[32][4] = {};
#pragma unroll
    for (int kt = 0; kt < 4; kt++) {
        uint32_t ah[4], al[4];
        ldmA(ah, qh, w * 16, kt * 16, lane, PS);
        ldmA(al, ql, w * 16, kt * 16, lane, PS);
#pragma unroll
        for (int nt = 0; nt < 32; nt += 2) {
            uint32_t bh[4], bl[4];
            ldmB2(bh, kh, nt * 8, kt * 16, lane, PS);
            ldmB2(bl, kl, nt * 8, kt * 16, lane, PS);
            mma16816(e[nt], ah, bh);
            mma16816(e[nt], ah, bl);
            mma16816(e[nt], al, bh);
            mma16816(e[nt + 1], ah, bh + 2);
            mma16816(e[nt + 1], ah, bl + 2);
            mma16816(e[nt + 1], al, bh + 2);
        }
    }
    __syncthreads();

    for (int i = tid; i < 4096; i += 256) {
        int o = i >> 5, s = (i & 31) * 8;
        CP16(sptr(vs1 + o * PSV + s), vg + (size_t)(o + 128) * HWn + s);
    }
    CPCOMMIT();

    float m0 = -1e30f, m1 = -1e30f;
#pragma unroll
    for (int nt = 0; nt < 32; nt++) {
        m0 = fmaxf(m0, fmaxf(e[nt][0], e[nt][1]));
        m1 = fmaxf(m1, fmaxf(e[nt][2], e[nt][3]));
    }
    m0 = fmaxf(m0, __shfl_xor_sync(0xffffffffu, m0, 1));
    m0 = fmaxf(m0, __shfl_xor_sync(0xffffffffu, m0, 2));
    m1 = fmaxf(m1, __shfl_xor_sync(0xffffffffu, m1, 1));
    m1 = fmaxf(m1, __shfl_xor_sync(0xffffffffu, m1, 2));

    float s0 = 0.f, s1 = 0.f;
    uint32_t ah_[64];
#pragma unroll
    for (int nt = 0; nt < 32; nt++) {
        float p00 = __expf(e[nt][0] - m0), p01 = __expf(e[nt][1] - m0);
        float p10 = __expf(e[nt][2] - m1), p11 = __expf(e[nt][3] - m1);
        s0 += p00 + p01;
        s1 += p10 + p11;
        ah_[2 * nt]     = pack2(__float2half_rn(p00), __float2half_rn(p01));
        ah_[2 * nt + 1] = pack2(__float2half_rn(p10), __float2half_rn(p11));
    }
    s0 += __shfl_xor_sync(0xffffffffu, s0, 1);
    s0 += __shfl_xor_sync(0xffffffffu, s0, 2);
    s1 += __shfl_xor_sync(0xffffffffu, s1, 1);
    s1 += __shfl_xor_sync(0xffffffffu, s1, 2);
    const float rinv0 = 1.0f / s0, rinv1 = 1.0f / s1;

    CPWAIT(1);
    __syncthreads();
    {
        float oacc[16][4] = {};
#pragma unroll
        for (int kt = 0; kt < 16; kt++) {
            const uint32_t* Ah = &ah_[4 * kt];
#pragma unroll
            for (int nt = 0; nt < 16; nt += 2) {
                uint32_t bb[4];
                ldmB2(bb, vs0, nt * 8, kt * 16, lane, PSV);
                mma16816(oacc[nt], Ah, bb);
                mma16816(oacc[nt + 1], Ah, bb + 2);
            }
        }
#pragma unroll
        for (int nt = 0; nt < 16; nt++) {
            int o = nt * 8 + 2 * c;
            size_t i0 = (size_t)(b * 256 + o) * HWn + h * Wn + w0 + w * 16 + g;
            out[i0]           = oacc[nt][0] * rinv0;
            out[i0 + HWn]     = oacc[nt][1] * rinv0;
            out[i0 + 8]       = oacc[nt][2] * rinv1;
            out[i0 + HWn + 8] = oacc[nt][3] * rinv1;
        }
    }

    CPWAIT(0);
    __syncthreads();
    {
        float oacc[16][4] = {};
#pragma unroll
        for (int kt = 0; kt < 16; kt++) {
            const uint32_t* Ah = &ah_[4 * kt];
#pragma unroll
            for (int nt = 0; nt < 16; nt += 2) {
                uint32_t bb[4];
                ldmB2(bb, vs1, nt * 8, kt * 16, lane, PSV);
                mma16816(oacc[nt], Ah, bb);
                mma16816(oacc[nt + 1], Ah, bb + 2);
            }
        }
#pragma unroll
        for (int nt = 0; nt < 16; nt++) {
            int o = 128 + nt * 8 + 2 * c;
            size_t i0 = (size_t)(b * 256 + o) * HWn + h * Wn + w0 + w * 16 + g;
            out[i0]           = oacc[nt][0] * rinv0;
            out[i0 + HWn]     = oacc[nt][1] * rinv0;
            out[i0 + 8]       = oacc[nt][2] * rinv1;
            out[i0 + HWn + 8] = oacc[nt][3] * rinv1;
        }
    }
}

// ---------------------------------------------------------------------------
extern "C" void kernel_launch(void* const* d_in, const int* in_sizes, int n_in,
                              void* d_out, int out_size)
{
    const float* flow   = (const float*)d_in[0];
    const float* de_out = (const float*)d_in[1];
    const float* Wq     = (const float*)d_in[2];
    const float* bq     = (const float*)d_in[3];
    const float* Wk     = (const float*)d_in[4];
    const float* bk     = (const float*)d_in[5];
    const float* Wv     = (const float*)d_in[6];
    const float* bv     = (const float*)d_in[7];
    float* out = (float*)d_out;

    cudaFuncSetAttribute(megaproj, cudaFuncAttributeMaxDynamicSharedMemorySize, MP_SMEM);
    cudaFuncSetAttribute(attn,     cudaFuncAttributeMaxDynamicSharedMemorySize, A_SMEM);

    prep<<<192, 256>>>(Wq, Wk, Wv);
    megaproj<<<dim3(4, HWn / 128, Bn), 256, MP_SMEM>>>(de_out, flow, bq, bk, bv);
    attn<<<dim3(Wn / 128, Hn, Bn), 256, A_SMEM>>>(out);
}